// round 6
// baseline (speedup 1.0000x reference)
#include <cuda_runtime.h>
#include <math.h>

// Problem dims
#define BB 4
#define TT 1024
#define EE 768
#define HH 6
#define HD 128
#define LL 6
#define VV 32000
#define BT (BB*TT)   // 4096
#define FF (4*EE)    // 3072

// Scratch (device globals -- no runtime allocation allowed)
__device__ float g_x[BT*EE];
__device__ float g_h[BT*EE];
__device__ float g_q[BT*EE];
__device__ float g_k[BT*EE];
__device__ float g_v[BT*EE];
__device__ float g_o[BT*EE];
__device__ float g_attn[(long)BB*HH*TT*TT];
__device__ float g_mlp[BT*FF];
__device__ float g_logits[(long)BT*VV];   // fallback logits buffer (d_out too small)
__device__ float g_lossrow[BT];

#define FLAG_RELU  1
#define FLAG_ACCUM 2

// ---------------------------------------------------------------------------
// Generic 128x128x8 tiled fp32 GEMM: C = A@B (+bias) (+C if ACCUM) (relu opt)
// Batched via blockIdx.z with split offsets: off = (z/zdiv)*outer + (z%zdiv)*inner
// All M,N divisible by 128 and K by 8 for every call in this model.
// ---------------------------------------------------------------------------
__global__ __launch_bounds__(256) void gemm128(
    const float* __restrict__ A, const float* __restrict__ B,
    float* __restrict__ C, const float* __restrict__ bias,
    int M, int N, int K, int lda, int ldb, int ldc,
    long sA, long sBo, long sBi, long sCo, long sCi, int zdiv, int flags)
{
    __shared__ float As[8][128];
    __shared__ float Bs[8][128];

    const int tid = threadIdx.x;
    const int tx = tid & 15, ty = tid >> 4;
    const int m0 = blockIdx.y * 128, n0 = blockIdx.x * 128;
    const int z = blockIdx.z;

    const float* Ab = A + (long)z * sA;
    const float* Bb = B + (long)(z / zdiv) * sBo + (long)(z % zdiv) * sBi;
    float*       Cb = C + (long)(z / zdiv) * sCo + (long)(z % zdiv) * sCi;

    float acc[8][8];
    #pragma unroll
    for (int i = 0; i < 8; i++)
        #pragma unroll
        for (int j = 0; j < 8; j++) acc[i][j] = 0.f;

    const int arow = tid >> 1;           // 0..127
    const int akq  = (tid & 1) * 4;      // 0 or 4
    const int brow = tid >> 5;           // 0..7
    const int bcol = (tid & 31) * 4;     // 0..124

    for (int kt = 0; kt < K; kt += 8) {
        float4 av = *(const float4*)&Ab[(long)(m0 + arow) * lda + kt + akq];
        float4 bv = *(const float4*)&Bb[(long)(kt + brow) * ldb + n0 + bcol];
        __syncthreads();
        As[akq + 0][arow] = av.x;
        As[akq + 1][arow] = av.y;
        As[akq + 2][arow] = av.z;
        As[akq + 3][arow] = av.w;
        *(float4*)&Bs[brow][bcol] = bv;
        __syncthreads();
        #pragma unroll
        for (int kk = 0; kk < 8; kk++) {
            float4 a0 = *(const float4*)&As[kk][ty * 8];
            float4 a1 = *(const float4*)&As[kk][ty * 8 + 4];
            float4 b0 = *(const float4*)&Bs[kk][tx * 8];
            float4 b1 = *(const float4*)&Bs[kk][tx * 8 + 4];
            float a[8] = {a0.x, a0.y, a0.z, a0.w, a1.x, a1.y, a1.z, a1.w};
            float b[8] = {b0.x, b0.y, b0.z, b0.w, b1.x, b1.y, b1.z, b1.w};
            #pragma unroll
            for (int i = 0; i < 8; i++)
                #pragma unroll
                for (int j = 0; j < 8; j++)
                    acc[i][j] += a[i] * b[j];
        }
    }

    float bj[8];
    #pragma unroll
    for (int j = 0; j < 8; j++)
        bj[j] = bias ? bias[n0 + tx * 8 + j] : 0.f;

    #pragma unroll
    for (int i = 0; i < 8; i++) {
        long crow = (long)(m0 + ty * 8 + i) * ldc + n0 + tx * 8;
        #pragma unroll
        for (int j = 0; j < 8; j++) {
            float vv = acc[i][j] + bj[j];
            if (flags & FLAG_ACCUM) vv += Cb[crow + j];
            if (flags & FLAG_RELU)  vv = fmaxf(vv, 0.f);
            Cb[crow + j] = vv;
        }
    }
}

// ---------------------------------------------------------------------------
// Embedding: x[b*T+t, :] = tok_emb[idx[b,t], :] + pos_emb[t, :]
// idx is int32 (harness narrows int64 inputs to int32).
// ---------------------------------------------------------------------------
__global__ void embed_kernel(const int* __restrict__ idx,
                             const float* __restrict__ tok,
                             const float* __restrict__ pos,
                             float* __restrict__ x)
{
    long i = (long)blockIdx.x * 256 + threadIdx.x;
    if (i >= (long)BT * EE) return;
    int row = (int)(i / EE);
    int col = (int)(i % EE);
    long tkn = idx[row];
    tkn = ((tkn % VV) + VV) % VV;   // defensive clamp (identity for valid data)
    x[i] = tok[tkn * EE + col] + pos[(long)(row % TT) * EE + col];
}

// ---------------------------------------------------------------------------
// LayerNorm (one block per row, 768 cols)
// ---------------------------------------------------------------------------
__global__ __launch_bounds__(256) void ln_kernel(
    const float* __restrict__ x, const float* __restrict__ s,
    const float* __restrict__ b, float* __restrict__ o)
{
    __shared__ float red[256];
    const int row = blockIdx.x;
    const int tid = threadIdx.x;
    const float* xr = x + (long)row * EE;

    float ls = 0.f;
    for (int c = tid; c < EE; c += 256) ls += xr[c];
    red[tid] = ls; __syncthreads();
    for (int st = 128; st > 0; st >>= 1) { if (tid < st) red[tid] += red[tid + st]; __syncthreads(); }
    float mu = red[0] / EE;
    __syncthreads();

    float lv = 0.f;
    for (int c = tid; c < EE; c += 256) { float d = xr[c] - mu; lv += d * d; }
    red[tid] = lv; __syncthreads();
    for (int st = 128; st > 0; st >>= 1) { if (tid < st) red[tid] += red[tid + st]; __syncthreads(); }
    float rs = rsqrtf(red[0] / EE + 1e-5f);

    float* orow = o + (long)row * EE;
    for (int c = tid; c < EE; c += 256)
        orow[c] = (xr[c] - mu) * rs * s[c] + b[c];
}

// ---------------------------------------------------------------------------
// Attention scores + causal softmax. One block per (query, head, batch).
// P[b,h,q,k] = softmax_k( (q.k)*scale, k<=q ), zeros for k>q.
// ---------------------------------------------------------------------------
__global__ __launch_bounds__(256) void attn_scores_kernel(
    const float* __restrict__ Q, const float* __restrict__ Km, float* __restrict__ P)
{
    __shared__ float4 qs[HD / 4];
    __shared__ float red[256];
    const int qi = blockIdx.x, h = blockIdx.y, b = blockIdx.z;
    const int tid = threadIdx.x;
    const float scale = 0.08838834764831845f;  // 1/sqrt(128)

    const float* qrow = Q + ((long)(b * TT + qi)) * EE + h * HD;
    if (tid < HD / 4) qs[tid] = ((const float4*)qrow)[tid];
    __syncthreads();

    float sc[4];
    float lm = -1e30f;
    #pragma unroll
    for (int j = 0; j < 4; j++) {
        int key = tid + j * 256;
        float d = -1e30f;
        if (key <= qi) {
            const float4* kr = (const float4*)(Km + ((long)(b * TT + key)) * EE + h * HD);
            float a = 0.f;
            #pragma unroll
            for (int u = 0; u < HD / 4; u++) {
                float4 kv = kr[u]; float4 qv = qs[u];
                a += kv.x * qv.x + kv.y * qv.y + kv.z * qv.z + kv.w * qv.w;
            }
            d = a * scale;
            lm = fmaxf(lm, d);
        }
        sc[j] = d;
    }
    red[tid] = lm; __syncthreads();
    for (int st = 128; st > 0; st >>= 1) { if (tid < st) red[tid] = fmaxf(red[tid], red[tid + st]); __syncthreads(); }
    float m = red[0];
    __syncthreads();

    float ssum = 0.f;
    #pragma unroll
    for (int j = 0; j < 4; j++) {
        if (sc[j] > -1e29f) { sc[j] = expf(sc[j] - m); ssum += sc[j]; }
        else sc[j] = 0.f;
    }
    red[tid] = ssum; __syncthreads();
    for (int st = 128; st > 0; st >>= 1) { if (tid < st) red[tid] += red[tid + st]; __syncthreads(); }
    float sinv = 1.f / red[0];

    float* prow = P + (((long)(b * HH + h) * TT + qi) * TT);
    #pragma unroll
    for (int j = 0; j < 4; j++)
        prow[tid + j * 256] = sc[j] * sinv;
}

// ---------------------------------------------------------------------------
// Loss: per-row log-softmax target pick, then reduction. tgt is int32.
// ---------------------------------------------------------------------------
__global__ __launch_bounds__(256) void lossrow_kernel(
    const float* __restrict__ logits, const int* __restrict__ tgt,
    float* __restrict__ lossrow)
{
    __shared__ float red[256];
    const int row = blockIdx.x;
    const int tid = threadIdx.x;
    const float* lr = logits + (long)row * VV;

    float lm = -1e30f;
    for (int c = tid; c < VV; c += 256) lm = fmaxf(lm, lr[c]);
    red[tid] = lm; __syncthreads();
    for (int st = 128; st > 0; st >>= 1) { if (tid < st) red[tid] = fmaxf(red[tid], red[tid + st]); __syncthreads(); }
    float m = red[0];
    __syncthreads();

    float ls = 0.f;
    for (int c = tid; c < VV; c += 256) ls += expf(lr[c] - m);
    red[tid] = ls; __syncthreads();
    for (int st = 128; st > 0; st >>= 1) { if (tid < st) red[tid] += red[tid + st]; __syncthreads(); }

    if (tid == 0) {
        long t = tgt[row];
        t = ((t % VV) + VV) % VV;   // defensive clamp
        lossrow[row] = lr[t] - m - logf(red[0]);
    }
}

// Fill the tail of the output buffer (everything past the logits) with the
// loss scalar; if the buffer holds no logits (out_size < BT*V), fill all of it.
__global__ __launch_bounds__(256) void lossfinal_kernel(
    const float* __restrict__ lossrow, float* __restrict__ dst, long count)
{
    __shared__ float red[256];
    const int tid = threadIdx.x;
    float ls = 0.f;
    for (int r = tid; r < BT; r += 256) ls += lossrow[r];
    red[tid] = ls; __syncthreads();
    for (int st = 128; st > 0; st >>= 1) { if (tid < st) red[tid] += red[tid + st]; __syncthreads(); }
    float loss = -red[0] / (float)BT;
    for (long i = tid; i < count; i += 256) dst[i] = loss;
}

// ---------------------------------------------------------------------------
// Host orchestration (graph-capturable: only kernel launches on default stream)
// ---------------------------------------------------------------------------
extern "C" void kernel_launch(void* const* d_in, const int* in_sizes, int n_in,
                              void* d_out, int out_size)
{
    const int* idx = (const int*)d_in[0];
    const int* tgt = (const int*)d_in[1];
    const float* tok  = (const float*)d_in[2];
    const float* pos  = (const float*)d_in[3];
    const float* Wq   = (const float*)d_in[4];
    const float* bq   = (const float*)d_in[5];
    const float* Wk   = (const float*)d_in[6];
    const float* bk   = (const float*)d_in[7];
    const float* Wv   = (const float*)d_in[8];
    const float* bv   = (const float*)d_in[9];
    const float* Wo   = (const float*)d_in[10];
    const float* bo   = (const float*)d_in[11];
    const float* w1   = (const float*)d_in[12];
    const float* b1   = (const float*)d_in[13];
    const float* w2   = (const float*)d_in[14];
    const float* b2   = (const float*)d_in[15];
    const float* ln1s = (const float*)d_in[16];
    const float* ln1b = (const float*)d_in[17];
    const float* ln2s = (const float*)d_in[18];
    const float* ln2b = (const float*)d_in[19];
    const float* lnfs = (const float*)d_in[20];
    const float* lnfb = (const float*)d_in[21];
    const float* Wlm  = (const float*)d_in[22];
    const float* blm  = (const float*)d_in[23];
    float* out = (float*)d_out;

    float *x, *h, *q, *k, *v, *o, *attn, *mlp, *logits, *lrow;
    cudaGetSymbolAddress((void**)&x,      g_x);
    cudaGetSymbolAddress((void**)&h,      g_h);
    cudaGetSymbolAddress((void**)&q,      g_q);
    cudaGetSymbolAddress((void**)&k,      g_k);
    cudaGetSymbolAddress((void**)&v,      g_v);
    cudaGetSymbolAddress((void**)&o,      g_o);
    cudaGetSymbolAddress((void**)&attn,   g_attn);
    cudaGetSymbolAddress((void**)&mlp,    g_mlp);
    cudaGetSymbolAddress((void**)&logits, g_logits);
    cudaGetSymbolAddress((void**)&lrow,   g_lossrow);

    const long BTV = (long)BT * VV;
    const long osz = (long)(unsigned)out_size;
    // Where do logits go? Directly into d_out only if they provably fit.
    float* logits_dst = (osz >= BTV) ? out : logits;

    embed_kernel<<<(BT * EE + 255) / 256, 256>>>(idx, tok, pos, x);

    dim3 gE(EE / 128, BT / 128, 1);      // [4096,768] outputs
    dim3 gF(FF / 128, BT / 128, 1);      // [4096,3072] outputs
    dim3 gAV(1, TT / 128, BB * HH);      // attn @ V
    dim3 gLM(VV / 128, BT / 128, 1);     // logits

    for (int l = 0; l < LL; l++) {
        long wofs = (long)l * EE * EE;
        ln_kernel<<<BT, 256>>>(x, ln1s + l * EE, ln1b + l * EE, h);
        gemm128<<<gE, 256>>>(h, Wq + wofs, q, bq + l * EE, BT, EE, EE, EE, EE, EE, 0, 0, 0, 0, 0, 1, 0);
        gemm128<<<gE, 256>>>(h, Wk + wofs, k, bk + l * EE, BT, EE, EE, EE, EE, EE, 0, 0, 0, 0, 0, 1, 0);
        gemm128<<<gE, 256>>>(h, Wv + wofs, v, bv + l * EE, BT, EE, EE, EE, EE, EE, 0, 0, 0, 0, 0, 1, 0);

        attn_scores_kernel<<<dim3(TT, HH, BB), 256>>>(q, k, attn);

        // o[b, q, h*HD:..] = P[b,h] @ v[b, :, h*HD:..]
        gemm128<<<gAV, 256>>>(attn, v, o, nullptr, TT, HD, TT, TT, EE, EE,
                              (long)TT * TT, (long)TT * EE, HD, (long)TT * EE, HD, HH, 0);

        gemm128<<<gE, 256>>>(o, Wo + wofs, x, bo + l * EE, BT, EE, EE, EE, EE, EE,
                             0, 0, 0, 0, 0, 1, FLAG_ACCUM);

        ln_kernel<<<BT, 256>>>(x, ln2s + l * EE, ln2b + l * EE, h);
        gemm128<<<gF, 256>>>(h, w1 + (long)l * EE * FF, mlp, b1 + (long)l * FF,
                             BT, FF, EE, EE, FF, FF, 0, 0, 0, 0, 0, 1, FLAG_RELU);
        gemm128<<<gE, 256>>>(mlp, w2 + (long)l * FF * EE, x, b2 + l * EE,
                             BT, EE, FF, FF, EE, EE, 0, 0, 0, 0, 0, 1, FLAG_ACCUM);
    }

    ln_kernel<<<BT, 256>>>(x, lnfs, lnfb, h);
    gemm128<<<gLM, 256>>>(h, Wlm, logits_dst, blm, BT, VV, EE, EE, VV, VV, 0, 0, 0, 0, 0, 1, 0);

    // Loss fills whatever part of d_out is not logits.
    lossrow_kernel<<<BT, 256>>>(logits_dst, tgt, lrow);
    if (osz > BTV) {
        lossfinal_kernel<<<1, 256>>>(lrow, out + BTV, osz - BTV);
    } else if (osz < BTV) {
        lossfinal_kernel<<<1, 256>>>(lrow, out, osz);
    }
}

// round 8
// speedup vs baseline: 2.2876x; 2.2876x over previous
#include <cuda_runtime.h>
#include <math.h>
#include <stdint.h>

// Problem dims
#define BB 4
#define TT 1024
#define EE 768
#define HH 6
#define HD 128
#define LL 6
#define VV 32000
#define BT (BB*TT)   // 4096
#define FF (4*EE)    // 3072

// Scratch (device globals -- no runtime allocation allowed)
__device__ float g_x[BT*EE];
__device__ float g_h[BT*EE];
__device__ float g_q[BT*EE];
__device__ float g_k[BT*EE];
__device__ float g_v[BT*EE];
__device__ float g_o[BT*EE];
__device__ float g_attn[(long)BB*HH*TT*TT];
__device__ float g_mlp[BT*FF];
__device__ float g_logits[(long)BT*VV];   // fallback logits buffer (d_out too small)
__device__ float g_lossrow[BT];

#define FLAG_RELU  1
#define FLAG_ACCUM 2

__device__ __forceinline__ float to_tf32(float x) {
    float r;
    asm("cvt.rna.tf32.f32 %0, %1;" : "=f"(r) : "f"(x));
    return r;
}

__device__ __forceinline__ void mma_tf32(float c[4], uint32_t a0, uint32_t a1,
                                         uint32_t a2, uint32_t a3,
                                         uint32_t b0, uint32_t b1) {
    asm volatile(
        "mma.sync.aligned.m16n8k8.row.col.f32.tf32.tf32.f32 "
        "{%0,%1,%2,%3}, {%4,%5,%6,%7}, {%8,%9}, {%0,%1,%2,%3};\n"
        : "+f"(c[0]), "+f"(c[1]), "+f"(c[2]), "+f"(c[3])
        : "r"(a0), "r"(a1), "r"(a2), "r"(a3), "r"(b0), "r"(b1));
}

// ---------------------------------------------------------------------------
// TF32 tensor-core GEMM: C = A@B (+bias) (+C if ACCUM) (relu opt)
// Block tile 128x128, K-step 32. 8 warps in 2(M)x4(N); warp tile 64x32 via
// 4x4 m16n8k8 mma. Smem stride 132 -> conflict-free fragment loads.
// Batched via blockIdx.z: off = (z/zdiv)*outer + (z%zdiv)*inner.
// Requires M%128==0, N%128==0, K%32==0 (true for all calls here).
// ---------------------------------------------------------------------------
__global__ __launch_bounds__(256) void gemm128(
    const float* __restrict__ A, const float* __restrict__ B,
    float* __restrict__ C, const float* __restrict__ bias,
    int M, int N, int K, int lda, int ldb, int ldc,
    long sA, long sBo, long sBi, long sCo, long sCi, int zdiv, int flags)
{
    __shared__ float As[32][132];   // [k][m]
    __shared__ float Bs[32][132];   // [k][n]

    const int tid  = threadIdx.x;
    const int lane = tid & 31;
    const int wid  = tid >> 5;
    const int warp_m = wid & 1;       // 0..1  (64 rows each)
    const int warp_n = wid >> 1;      // 0..3  (32 cols each)
    const int m0 = blockIdx.y * 128, n0 = blockIdx.x * 128;
    const int z = blockIdx.z;

    const float* Ab = A + (long)z * sA;
    const float* Bb = B + (long)(z / zdiv) * sBo + (long)(z % zdiv) * sBi;
    float*       Cb = C + (long)(z / zdiv) * sCo + (long)(z % zdiv) * sCi;

    // Global-load assignments
    const int a_r  = tid >> 1;            // row 0..127
    const int a_q0 = (tid & 1) * 16;      // k offset 0 or 16 (4 float4 each)
    const int b_k  = tid >> 3;            // k 0..31
    const int b_n0 = (tid & 7) * 16;      // n offset (4 float4 each)

    // Fragment-load lane coords
    const int fr = lane >> 2;   // 0..7
    const int fc = lane & 3;    // 0..3

    float acc[4][4][4];
    #pragma unroll
    for (int i = 0; i < 4; i++)
        #pragma unroll
        for (int j = 0; j < 4; j++)
            #pragma unroll
            for (int u = 0; u < 4; u++) acc[i][j][u] = 0.f;

    float4 av[4], bv[4];

    // Prologue: fetch + store tile 0
    #pragma unroll
    for (int i = 0; i < 4; i++) {
        av[i] = *(const float4*)&Ab[(long)(m0 + a_r) * lda + a_q0 + i * 4];
        bv[i] = *(const float4*)&Bb[(long)b_k * ldb + n0 + b_n0 + i * 4];
    }
    #pragma unroll
    for (int i = 0; i < 4; i++) {
        As[a_q0 + i * 4 + 0][a_r] = to_tf32(av[i].x);
        As[a_q0 + i * 4 + 1][a_r] = to_tf32(av[i].y);
        As[a_q0 + i * 4 + 2][a_r] = to_tf32(av[i].z);
        As[a_q0 + i * 4 + 3][a_r] = to_tf32(av[i].w);
        float4 t = make_float4(to_tf32(bv[i].x), to_tf32(bv[i].y),
                               to_tf32(bv[i].z), to_tf32(bv[i].w));
        *(float4*)&Bs[b_k][b_n0 + i * 4] = t;
    }
    __syncthreads();

    for (int kt = 0; kt < K; kt += 32) {
        const bool has_next = (kt + 32) < K;
        if (has_next) {
            #pragma unroll
            for (int i = 0; i < 4; i++) {
                av[i] = *(const float4*)&Ab[(long)(m0 + a_r) * lda + kt + 32 + a_q0 + i * 4];
                bv[i] = *(const float4*)&Bb[(long)(kt + 32 + b_k) * ldb + n0 + b_n0 + i * 4];
            }
        }

        #pragma unroll
        for (int ks = 0; ks < 4; ks++) {
            const int kk = ks * 8;
            uint32_t afr[4][4];
            #pragma unroll
            for (int mt = 0; mt < 4; mt++) {
                int mb = warp_m * 64 + mt * 16 + fr;
                afr[mt][0] = __float_as_uint(As[kk + fc    ][mb]);
                afr[mt][1] = __float_as_uint(As[kk + fc    ][mb + 8]);
                afr[mt][2] = __float_as_uint(As[kk + fc + 4][mb]);
                afr[mt][3] = __float_as_uint(As[kk + fc + 4][mb + 8]);
            }
            uint32_t bfr[4][2];
            #pragma unroll
            for (int nt = 0; nt < 4; nt++) {
                int nb = warp_n * 32 + nt * 8 + fr;
                bfr[nt][0] = __float_as_uint(Bs[kk + fc    ][nb]);
                bfr[nt][1] = __float_as_uint(Bs[kk + fc + 4][nb]);
            }
            #pragma unroll
            for (int mt = 0; mt < 4; mt++)
                #pragma unroll
                for (int nt = 0; nt < 4; nt++)
                    mma_tf32(acc[mt][nt], afr[mt][0], afr[mt][1], afr[mt][2], afr[mt][3],
                             bfr[nt][0], bfr[nt][1]);
        }
        __syncthreads();

        if (has_next) {
            #pragma unroll
            for (int i = 0; i < 4; i++) {
                As[a_q0 + i * 4 + 0][a_r] = to_tf32(av[i].x);
                As[a_q0 + i * 4 + 1][a_r] = to_tf32(av[i].y);
                As[a_q0 + i * 4 + 2][a_r] = to_tf32(av[i].z);
                As[a_q0 + i * 4 + 3][a_r] = to_tf32(av[i].w);
                float4 t = make_float4(to_tf32(bv[i].x), to_tf32(bv[i].y),
                                       to_tf32(bv[i].z), to_tf32(bv[i].w));
                *(float4*)&Bs[b_k][b_n0 + i * 4] = t;
            }
            __syncthreads();
        }
    }

    // Epilogue
    #pragma unroll
    for (int nt = 0; nt < 4; nt++) {
        const int col = n0 + warp_n * 32 + nt * 8 + fc * 2;
        float bj0 = bias ? bias[col]     : 0.f;
        float bj1 = bias ? bias[col + 1] : 0.f;
        #pragma unroll
        for (int mt = 0; mt < 4; mt++) {
            const int row = m0 + warp_m * 64 + mt * 16 + fr;
            #pragma unroll
            for (int half = 0; half < 2; half++) {
                long base = (long)(row + half * 8) * ldc + col;
                float v0 = acc[mt][nt][half * 2 + 0] + bj0;
                float v1 = acc[mt][nt][half * 2 + 1] + bj1;
                if (flags & FLAG_ACCUM) { v0 += Cb[base]; v1 += Cb[base + 1]; }
                if (flags & FLAG_RELU)  { v0 = fmaxf(v0, 0.f); v1 = fmaxf(v1, 0.f); }
                Cb[base]     = v0;
                Cb[base + 1] = v1;
            }
        }
    }
}

// ---------------------------------------------------------------------------
// Embedding: x[b*T+t, :] = tok_emb[idx[b,t], :] + pos_emb[t, :]  (idx int32)
// ---------------------------------------------------------------------------
__global__ void embed_kernel(const int* __restrict__ idx,
                             const float* __restrict__ tok,
                             const float* __restrict__ pos,
                             float* __restrict__ x)
{
    long i = (long)blockIdx.x * 256 + threadIdx.x;
    if (i >= (long)BT * EE) return;
    int row = (int)(i / EE);
    int col = (int)(i % EE);
    long tkn = idx[row];
    tkn = ((tkn % VV) + VV) % VV;   // defensive clamp (identity for valid data)
    x[i] = tok[tkn * EE + col] + pos[(long)(row % TT) * EE + col];
}

// ---------------------------------------------------------------------------
// LayerNorm (one block per row, 768 cols)
// ---------------------------------------------------------------------------
__global__ __launch_bounds__(256) void ln_kernel(
    const float* __restrict__ x, const float* __restrict__ s,
    const float* __restrict__ b, float* __restrict__ o)
{
    __shared__ float red[256];
    const int row = blockIdx.x;
    const int tid = threadIdx.x;
    const float* xr = x + (long)row * EE;

    float ls = 0.f;
    for (int c = tid; c < EE; c += 256) ls += xr[c];
    red[tid] = ls; __syncthreads();
    for (int st = 128; st > 0; st >>= 1) { if (tid < st) red[tid] += red[tid + st]; __syncthreads(); }
    float mu = red[0] / EE;
    __syncthreads();

    float lv = 0.f;
    for (int c = tid; c < EE; c += 256) { float d = xr[c] - mu; lv += d * d; }
    red[tid] = lv; __syncthreads();
    for (int st = 128; st > 0; st >>= 1) { if (tid < st) red[tid] += red[tid + st]; __syncthreads(); }
    float rs = rsqrtf(red[0] / EE + 1e-5f);

    float* orow = o + (long)row * EE;
    for (int c = tid; c < EE; c += 256)
        orow[c] = (xr[c] - mu) * rs * s[c] + b[c];
}

// ---------------------------------------------------------------------------
// Attention scores + causal softmax. One block per (query, head, batch).
// ---------------------------------------------------------------------------
__global__ __launch_bounds__(256) void attn_scores_kernel(
    const float* __restrict__ Q, const float* __restrict__ Km, float* __restrict__ P)
{
    __shared__ float4 qs[HD / 4];
    __shared__ float red[256];
    const int qi = blockIdx.x, h = blockIdx.y, b = blockIdx.z;
    const int tid = threadIdx.x;
    const float scale = 0.08838834764831845f;  // 1/sqrt(128)

    const float* qrow = Q + ((long)(b * TT + qi)) * EE + h * HD;
    if (tid < HD / 4) qs[tid] = ((const float4*)qrow)[tid];
    __syncthreads();

    float sc[4];
    float lm = -1e30f;
    #pragma unroll
    for (int j = 0; j < 4; j++) {
        int key = tid + j * 256;
        float d = -1e30f;
        if (key <= qi) {
            const float4* kr = (const float4*)(Km + ((long)(b * TT + key)) * EE + h * HD);
            float a = 0.f;
            #pragma unroll
            for (int u = 0; u < HD / 4; u++) {
                float4 kv = kr[u]; float4 qv = qs[u];
                a += kv.x * qv.x + kv.y * qv.y + kv.z * qv.z + kv.w * qv.w;
            }
            d = a * scale;
            lm = fmaxf(lm, d);
        }
        sc[j] = d;
    }
    red[tid] = lm; __syncthreads();
    for (int st = 128; st > 0; st >>= 1) { if (tid < st) red[tid] = fmaxf(red[tid], red[tid + st]); __syncthreads(); }
    float m = red[0];
    __syncthreads();

    float ssum = 0.f;
    #pragma unroll
    for (int j = 0; j < 4; j++) {
        if (sc[j] > -1e29f) { sc[j] = expf(sc[j] - m); ssum += sc[j]; }
        else sc[j] = 0.f;
    }
    red[tid] = ssum; __syncthreads();
    for (int st = 128; st > 0; st >>= 1) { if (tid < st) red[tid] += red[tid + st]; __syncthreads(); }
    float sinv = 1.f / red[0];

    float* prow = P + (((long)(b * HH + h) * TT + qi) * TT);
    #pragma unroll
    for (int j = 0; j < 4; j++)
        prow[tid + j * 256] = sc[j] * sinv;
}

// ---------------------------------------------------------------------------
// Loss: per-row log-softmax target pick, then reduction. tgt is int32.
// ---------------------------------------------------------------------------
__global__ __launch_bounds__(256) void lossrow_kernel(
    const float* __restrict__ logits, const int* __restrict__ tgt,
    float* __restrict__ lossrow)
{
    __shared__ float red[256];
    const int row = blockIdx.x;
    const int tid = threadIdx.x;
    const float* lr = logits + (long)row * VV;

    float lm = -1e30f;
    for (int c = tid; c < VV; c += 256) lm = fmaxf(lm, lr[c]);
    red[tid] = lm; __syncthreads();
    for (int st = 128; st > 0; st >>= 1) { if (tid < st) red[tid] = fmaxf(red[tid], red[tid + st]); __syncthreads(); }
    float m = red[0];
    __syncthreads();

    float ls = 0.f;
    for (int c = tid; c < VV; c += 256) ls += expf(lr[c] - m);
    red[tid] = ls; __syncthreads();
    for (int st = 128; st > 0; st >>= 1) { if (tid < st) red[tid] += red[tid + st]; __syncthreads(); }

    if (tid == 0) {
        long t = tgt[row];
        t = ((t % VV) + VV) % VV;   // defensive clamp
        lossrow[row] = lr[t] - m - logf(red[0]);
    }
}

__global__ __launch_bounds__(256) void lossfinal_kernel(
    const float* __restrict__ lossrow, float* __restrict__ dst, long count)
{
    __shared__ float red[256];
    const int tid = threadIdx.x;
    float ls = 0.f;
    for (int r = tid; r < BT; r += 256) ls += lossrow[r];
    red[tid] = ls; __syncthreads();
    for (int st = 128; st > 0; st >>= 1) { if (tid < st) red[tid] += red[tid + st]; __syncthreads(); }
    float loss = -red[0] / (float)BT;
    for (long i = tid; i < count; i += 256) dst[i] = loss;
}

// ---------------------------------------------------------------------------
// Host orchestration (graph-capturable: only kernel launches)
// ---------------------------------------------------------------------------
extern "C" void kernel_launch(void* const* d_in, const int* in_sizes, int n_in,
                              void* d_out, int out_size)
{
    const int* idx = (const int*)d_in[0];
    const int* tgt = (const int*)d_in[1];
    const float* tok  = (const float*)d_in[2];
    const float* pos  = (const float*)d_in[3];
    const float* Wq   = (const float*)d_in[4];
    const float* bq   = (const float*)d_in[5];
    const float* Wk   = (const float*)d_in[6];
    const float* bk   = (const float*)d_in[7];
    const float* Wv   = (const float*)d_in[8];
    const float* bv   = (const float*)d_in[9];
    const float* Wo   = (const float*)d_in[10];
    const float* bo   = (const float*)d_in[11];
    const float* w1   = (const float*)d_in[12];
    const float* b1   = (const float*)d_in[13];
    const float* w2   = (const float*)d_in[14];
    const float* b2   = (const float*)d_in[15];
    const float* ln1s = (const float*)d_in[16];
    const float* ln1b = (const float*)d_in[17];
    const float* ln2s = (const float*)d_in[18];
    const float* ln2b = (const float*)d_in[19];
    const float* lnfs = (const float*)d_in[20];
    const float* lnfb = (const float*)d_in[21];
    const float* Wlm  = (const float*)d_in[22];
    const float* blm  = (const float*)d_in[23];
    float* out = (float*)d_out;

    float *x, *h, *q, *k, *v, *o, *attn, *mlp, *logits, *lrow;
    cudaGetSymbolAddress((void**)&x,      g_x);
    cudaGetSymbolAddress((void**)&h,      g_h);
    cudaGetSymbolAddress((void**)&q,      g_q);
    cudaGetSymbolAddress((void**)&k,      g_k);
    cudaGetSymbolAddress((void**)&v,      g_v);
    cudaGetSymbolAddress((void**)&o,      g_o);
    cudaGetSymbolAddress((void**)&attn,   g_attn);
    cudaGetSymbolAddress((void**)&mlp,    g_mlp);
    cudaGetSymbolAddress((void**)&logits, g_logits);
    cudaGetSymbolAddress((void**)&lrow,   g_lossrow);

    const long BTV = (long)BT * VV;
    const long osz = (long)(unsigned)out_size;
    float* logits_dst = (osz >= BTV) ? out : logits;

    embed_kernel<<<(BT * EE + 255) / 256, 256>>>(idx, tok, pos, x);

    dim3 gE(EE / 128, BT / 128, 1);      // [4096,768] outputs
    dim3 gF(FF / 128, BT / 128, 1);      // [4096,3072] outputs
    dim3 gAV(1, TT / 128, BB * HH);      // attn @ V
    dim3 gLM(VV / 128, BT / 128, 1);     // logits

    for (int l = 0; l < LL; l++) {
        long wofs = (long)l * EE * EE;
        ln_kernel<<<BT, 256>>>(x, ln1s + l * EE, ln1b + l * EE, h);
        gemm128<<<gE, 256>>>(h, Wq + wofs, q, bq + l * EE, BT, EE, EE, EE, EE, EE, 0, 0, 0, 0, 0, 1, 0);
        gemm128<<<gE, 256>>>(h, Wk + wofs, k, bk + l * EE, BT, EE, EE, EE, EE, EE, 0, 0, 0, 0, 0, 1, 0);
        gemm128<<<gE, 256>>>(h, Wv + wofs, v, bv + l * EE, BT, EE, EE, EE, EE, EE, 0, 0, 0, 0, 0, 1, 0);

        attn_scores_kernel<<<dim3(TT, HH, BB), 256>>>(q, k, attn);

        // o[b, q, h*HD:..] = P[b,h] @ v[b, :, h*HD:..]
        gemm128<<<gAV, 256>>>(attn, v, o, nullptr, TT, HD, TT, TT, EE, EE,
                              (long)TT * TT, (long)TT * EE, HD, (long)TT * EE, HD, HH, 0);

        gemm128<<<gE, 256>>>(o, Wo + wofs, x, bo + l * EE, BT, EE, EE, EE, EE, EE,
                             0, 0, 0, 0, 0, 1, FLAG_ACCUM);

        ln_kernel<<<BT, 256>>>(x, ln2s + l * EE, ln2b + l * EE, h);
        gemm128<<<gF, 256>>>(h, w1 + (long)l * EE * FF, mlp, b1 + (long)l * FF,
                             BT, FF, EE, EE, FF, FF, 0, 0, 0, 0, 0, 1, FLAG_RELU);
        gemm128<<<gE, 256>>>(mlp, w2 + (long)l * FF * EE, x, b2 + l * EE,
                             BT, EE, FF, FF, EE, EE, 0, 0, 0, 0, 0, 1, FLAG_ACCUM);
    }

    ln_kernel<<<BT, 256>>>(x, lnfs, lnfb, h);
    gemm128<<<gLM, 256>>>(h, Wlm, logits_dst, blm, BT, VV, EE, EE, VV, VV, 0, 0, 0, 0, 0, 1, 0);

    lossrow_kernel<<<BT, 256>>>(logits_dst, tgt, lrow);
    if (osz > BTV) {
        lossfinal_kernel<<<1, 256>>>(lrow, out + BTV, osz - BTV);
    } else if (osz < BTV) {
        lossfinal_kernel<<<1, 256>>>(lrow, out, osz);
    }
}

// round 9
// speedup vs baseline: 2.3362x; 1.0212x over previous
#include <cuda_runtime.h>
#include <math.h>
#include <stdint.h>

// Problem dims
#define BB 4
#define TT 1024
#define EE 768
#define HH 6
#define HD 128
#define LL 6
#define VV 32000
#define BT (BB*TT)   // 4096
#define FF (4*EE)    // 3072

// Scratch (device globals -- no runtime allocation allowed)
__device__ float g_x[BT*EE];
__device__ float g_h[BT*EE];
__device__ float g_q[BT*EE];
__device__ float g_k[BT*EE];
__device__ float g_v[BT*EE];
__device__ float g_o[BT*EE];
__device__ float g_attn[(long)BB*HH*TT*TT];
__device__ float g_mlp[BT*FF];
__device__ float g_logits[(long)BT*VV];
__device__ float g_lossrow[BT];

#define FLAG_RELU  1
#define FLAG_ACCUM 2

// Dynamic smem: 2 stages x (As 32x132 + Bs 32x132) floats
#define STAGE_F   (32*132)
#define SMEM_F    (4*STAGE_F)
#define SMEM_BYTES (SMEM_F*4)

__device__ __forceinline__ float to_tf32(float x) {
    float r;
    asm("cvt.rna.tf32.f32 %0, %1;" : "=f"(r) : "f"(x));
    return r;
}

__device__ __forceinline__ void mma_tf32(float c[4], uint32_t a0, uint32_t a1,
                                         uint32_t a2, uint32_t a3,
                                         uint32_t b0, uint32_t b1) {
    asm volatile(
        "mma.sync.aligned.m16n8k8.row.col.f32.tf32.tf32.f32 "
        "{%0,%1,%2,%3}, {%4,%5,%6,%7}, {%8,%9}, {%0,%1,%2,%3};\n"
        : "+f"(c[0]), "+f"(c[1]), "+f"(c[2]), "+f"(c[3])
        : "r"(a0), "r"(a1), "r"(a2), "r"(a3), "r"(b0), "r"(b1));
}

// ---------------------------------------------------------------------------
// TF32 tensor-core GEMM core: 128x128 block tile, K-step 32, 2-stage smem
// pipeline (one __syncthreads per K-iter). 8 warps 2(M)x4(N), warp tile 64x32
// via 4x4 m16n8k8. Requires M%128==0 (per tile), N%128==0, K%32==0.
// ---------------------------------------------------------------------------
__device__ __forceinline__ void gemm_core(
    const float* __restrict__ Ab, const float* __restrict__ Bb,
    float* __restrict__ Cb, const float* __restrict__ bias,
    int K, int lda, int ldb, int ldc, int m0, int n0, int flags, float* sm)
{
    float* As = sm;              // [2][32][132]
    float* Bs = sm + 2*STAGE_F;  // [2][32][132]

    const int tid  = threadIdx.x;
    const int lane = tid & 31;
    const int wid  = tid >> 5;
    const int warp_m = wid & 1;
    const int warp_n = wid >> 1;

    const int a_r  = tid >> 1;
    const int a_q0 = (tid & 1) * 16;
    const int b_k  = tid >> 3;
    const int b_n0 = (tid & 7) * 16;

    const int fr = lane >> 2;
    const int fc = lane & 3;

    float acc[4][4][4];
    #pragma unroll
    for (int i = 0; i < 4; i++)
        #pragma unroll
        for (int j = 0; j < 4; j++)
            #pragma unroll
            for (int u = 0; u < 4; u++) acc[i][j][u] = 0.f;

    float4 av[4], bv[4];

    // Prologue: stage 0
    #pragma unroll
    for (int i = 0; i < 4; i++) {
        av[i] = *(const float4*)&Ab[(long)(m0 + a_r) * lda + a_q0 + i * 4];
        bv[i] = *(const float4*)&Bb[(long)b_k * ldb + n0 + b_n0 + i * 4];
    }
    #pragma unroll
    for (int i = 0; i < 4; i++) {
        As[(a_q0 + i*4 + 0)*132 + a_r] = to_tf32(av[i].x);
        As[(a_q0 + i*4 + 1)*132 + a_r] = to_tf32(av[i].y);
        As[(a_q0 + i*4 + 2)*132 + a_r] = to_tf32(av[i].z);
        As[(a_q0 + i*4 + 3)*132 + a_r] = to_tf32(av[i].w);
        float4 t = make_float4(to_tf32(bv[i].x), to_tf32(bv[i].y),
                               to_tf32(bv[i].z), to_tf32(bv[i].w));
        *(float4*)&Bs[b_k*132 + b_n0 + i*4] = t;
    }
    __syncthreads();

    int s = 0;
    for (int kt = 0; kt < K; kt += 32) {
        const bool has_next = (kt + 32) < K;
        if (has_next) {
            #pragma unroll
            for (int i = 0; i < 4; i++) {
                av[i] = *(const float4*)&Ab[(long)(m0 + a_r) * lda + kt + 32 + a_q0 + i * 4];
                bv[i] = *(const float4*)&Bb[(long)(kt + 32 + b_k) * ldb + n0 + b_n0 + i * 4];
            }
        }

        const float* As_s = As + s * STAGE_F;
        const float* Bs_s = Bs + s * STAGE_F;
        #pragma unroll
        for (int ks = 0; ks < 4; ks++) {
            const int kk = ks * 8;
            uint32_t afr[4][4];
            #pragma unroll
            for (int mt = 0; mt < 4; mt++) {
                int mb = warp_m * 64 + mt * 16 + fr;
                afr[mt][0] = __float_as_uint(As_s[(kk + fc    )*132 + mb]);
                afr[mt][1] = __float_as_uint(As_s[(kk + fc    )*132 + mb + 8]);
                afr[mt][2] = __float_as_uint(As_s[(kk + fc + 4)*132 + mb]);
                afr[mt][3] = __float_as_uint(As_s[(kk + fc + 4)*132 + mb + 8]);
            }
            uint32_t bfr[4][2];
            #pragma unroll
            for (int nt = 0; nt < 4; nt++) {
                int nb = warp_n * 32 + nt * 8 + fr;
                bfr[nt][0] = __float_as_uint(Bs_s[(kk + fc    )*132 + nb]);
                bfr[nt][1] = __float_as_uint(Bs_s[(kk + fc + 4)*132 + nb]);
            }
            #pragma unroll
            for (int mt = 0; mt < 4; mt++)
                #pragma unroll
                for (int nt = 0; nt < 4; nt++)
                    mma_tf32(acc[mt][nt], afr[mt][0], afr[mt][1], afr[mt][2], afr[mt][3],
                             bfr[nt][0], bfr[nt][1]);
        }

        if (has_next) {
            float* An = As + (s ^ 1) * STAGE_F;
            float* Bn = Bs + (s ^ 1) * STAGE_F;
            #pragma unroll
            for (int i = 0; i < 4; i++) {
                An[(a_q0 + i*4 + 0)*132 + a_r] = to_tf32(av[i].x);
                An[(a_q0 + i*4 + 1)*132 + a_r] = to_tf32(av[i].y);
                An[(a_q0 + i*4 + 2)*132 + a_r] = to_tf32(av[i].z);
                An[(a_q0 + i*4 + 3)*132 + a_r] = to_tf32(av[i].w);
                float4 t = make_float4(to_tf32(bv[i].x), to_tf32(bv[i].y),
                                       to_tf32(bv[i].z), to_tf32(bv[i].w));
                *(float4*)&Bn[b_k*132 + b_n0 + i*4] = t;
            }
            __syncthreads();
        }
        s ^= 1;
    }

    // Epilogue
    #pragma unroll
    for (int nt = 0; nt < 4; nt++) {
        const int col = n0 + warp_n * 32 + nt * 8 + fc * 2;
        float bj0 = bias ? bias[col]     : 0.f;
        float bj1 = bias ? bias[col + 1] : 0.f;
        #pragma unroll
        for (int mt = 0; mt < 4; mt++) {
            const int row = m0 + warp_m * 64 + mt * 16 + fr;
            #pragma unroll
            for (int half = 0; half < 2; half++) {
                long base = (long)(row + half * 8) * ldc + col;
                float v0 = acc[mt][nt][half * 2 + 0] + bj0;
                float v1 = acc[mt][nt][half * 2 + 1] + bj1;
                if (flags & FLAG_ACCUM) { v0 += Cb[base]; v1 += Cb[base + 1]; }
                if (flags & FLAG_RELU)  { v0 = fmaxf(v0, 0.f); v1 = fmaxf(v1, 0.f); }
                Cb[base]     = v0;
                Cb[base + 1] = v1;
            }
        }
    }
}

// Generic strided/batched wrapper (same interface as before)
__global__ __launch_bounds__(256) void gemm128(
    const float* __restrict__ A, const float* __restrict__ B,
    float* __restrict__ C, const float* __restrict__ bias,
    int M, int N, int K, int lda, int ldb, int ldc,
    long sA, long sBo, long sBi, long sCo, long sCi, int zdiv, int flags)
{
    extern __shared__ float sm[];
    const int z = blockIdx.z;
    const float* Ab = A + (long)z * sA;
    const float* Bb = B + (long)(z / zdiv) * sBo + (long)(z % zdiv) * sBi;
    float*       Cb = C + (long)(z / zdiv) * sCo + (long)(z % zdiv) * sCi;
    gemm_core(Ab, Bb, Cb, bias, K, lda, ldb, ldc,
              blockIdx.y * 128, blockIdx.x * 128, flags, sm);
}

// Fused QKV: one launch, z in {0,1,2} selects weight/output set (wave packing)
__global__ __launch_bounds__(256) void gemm_qkv(
    const float* __restrict__ A,
    const float* __restrict__ B0, const float* __restrict__ B1, const float* __restrict__ B2,
    float* __restrict__ C0, float* __restrict__ C1, float* __restrict__ C2,
    const float* __restrict__ bi0, const float* __restrict__ bi1, const float* __restrict__ bi2)
{
    extern __shared__ float sm[];
    const int z = blockIdx.z;
    const float* Bb = (z == 0) ? B0 : (z == 1) ? B1 : B2;
    float*       Cb = (z == 0) ? C0 : (z == 1) ? C1 : C2;
    const float* bi = (z == 0) ? bi0 : (z == 1) ? bi1 : bi2;
    gemm_core(A, Bb, Cb, bi, EE, EE, EE, EE,
              blockIdx.y * 128, blockIdx.x * 128, 0, sm);
}

// ---------------------------------------------------------------------------
// Embedding
// ---------------------------------------------------------------------------
__global__ void embed_kernel(const int* __restrict__ idx,
                             const float* __restrict__ tok,
                             const float* __restrict__ pos,
                             float* __restrict__ x)
{
    long i = (long)blockIdx.x * 256 + threadIdx.x;
    if (i >= (long)BT * EE) return;
    int row = (int)(i / EE);
    int col = (int)(i % EE);
    long tkn = idx[row];
    tkn = ((tkn % VV) + VV) % VV;
    x[i] = tok[tkn * EE + col] + pos[(long)(row % TT) * EE + col];
}

// ---------------------------------------------------------------------------
// LayerNorm
// ---------------------------------------------------------------------------
__global__ __launch_bounds__(256) void ln_kernel(
    const float* __restrict__ x, const float* __restrict__ s,
    const float* __restrict__ b, float* __restrict__ o)
{
    __shared__ float red[256];
    const int row = blockIdx.x;
    const int tid = threadIdx.x;
    const float* xr = x + (long)row * EE;

    float ls = 0.f;
    for (int c = tid; c < EE; c += 256) ls += xr[c];
    red[tid] = ls; __syncthreads();
    for (int st = 128; st > 0; st >>= 1) { if (tid < st) red[tid] += red[tid + st]; __syncthreads(); }
    float mu = red[0] / EE;
    __syncthreads();

    float lv = 0.f;
    for (int c = tid; c < EE; c += 256) { float d = xr[c] - mu; lv += d * d; }
    red[tid] = lv; __syncthreads();
    for (int st = 128; st > 0; st >>= 1) { if (tid < st) red[tid] += red[tid + st]; __syncthreads(); }
    float rs = rsqrtf(red[0] / EE + 1e-5f);

    float* orow = o + (long)row * EE;
    for (int c = tid; c < EE; c += 256)
        orow[c] = (xr[c] - mu) * rs * s[c] + b[c];
}

// ---------------------------------------------------------------------------
// Attention scores + causal softmax
// ---------------------------------------------------------------------------
__global__ __launch_bounds__(256) void attn_scores_kernel(
    const float* __restrict__ Q, const float* __restrict__ Km, float* __restrict__ P)
{
    __shared__ float4 qs[HD / 4];
    __shared__ float red[256];
    const int qi = blockIdx.x, h = blockIdx.y, b = blockIdx.z;
    const int tid = threadIdx.x;
    const float scale = 0.08838834764831845f;

    const float* qrow = Q + ((long)(b * TT + qi)) * EE + h * HD;
    if (tid < HD / 4) qs[tid] = ((const float4*)qrow)[tid];
    __syncthreads();

    float sc[4];
    float lm = -1e30f;
    #pragma unroll
    for (int j = 0; j < 4; j++) {
        int key = tid + j * 256;
        float d = -1e30f;
        if (key <= qi) {
            const float4* kr = (const float4*)(Km + ((long)(b * TT + key)) * EE + h * HD);
            float a = 0.f;
            #pragma unroll
            for (int u = 0; u < HD / 4; u++) {
                float4 kv = kr[u]; float4 qv = qs[u];
                a += kv.x * qv.x + kv.y * qv.y + kv.z * qv.z + kv.w * qv.w;
            }
            d = a * scale;
            lm = fmaxf(lm, d);
        }
        sc[j] = d;
    }
    red[tid] = lm; __syncthreads();
    for (int st = 128; st > 0; st >>= 1) { if (tid < st) red[tid] = fmaxf(red[tid], red[tid + st]); __syncthreads(); }
    float m = red[0];
    __syncthreads();

    float ssum = 0.f;
    #pragma unroll
    for (int j = 0; j < 4; j++) {
        if (sc[j] > -1e29f) { sc[j] = expf(sc[j] - m); ssum += sc[j]; }
        else sc[j] = 0.f;
    }
    red[tid] = ssum; __syncthreads();
    for (int st = 128; st > 0; st >>= 1) { if (tid < st) red[tid] += red[tid + st]; __syncthreads(); }
    float sinv = 1.f / red[0];

    float* prow = P + (((long)(b * HH + h) * TT + qi) * TT);
    #pragma unroll
    for (int j = 0; j < 4; j++)
        prow[tid + j * 256] = sc[j] * sinv;
}

// ---------------------------------------------------------------------------
// Loss
// ---------------------------------------------------------------------------
__global__ __launch_bounds__(256) void lossrow_kernel(
    const float* __restrict__ logits, const int* __restrict__ tgt,
    float* __restrict__ lossrow)
{
    __shared__ float red[256];
    const int row = blockIdx.x;
    const int tid = threadIdx.x;
    const float* lr = logits + (long)row * VV;

    float lm = -1e30f;
    for (int c = tid; c < VV; c += 256) lm = fmaxf(lm, lr[c]);
    red[tid] = lm; __syncthreads();
    for (int st = 128; st > 0; st >>= 1) { if (tid < st) red[tid] = fmaxf(red[tid], red[tid + st]); __syncthreads(); }
    float m = red[0];
    __syncthreads();

    float ls = 0.f;
    for (int c = tid; c < VV; c += 256) ls += expf(lr[c] - m);
    red[tid] = ls; __syncthreads();
    for (int st = 128; st > 0; st >>= 1) { if (tid < st) red[tid] += red[tid + st]; __syncthreads(); }

    if (tid == 0) {
        long t = tgt[row];
        t = ((t % VV) + VV) % VV;
        lossrow[row] = lr[t] - m - logf(red[0]);
    }
}

__global__ __launch_bounds__(256) void lossfinal_kernel(
    const float* __restrict__ lossrow, float* __restrict__ dst, long count)
{
    __shared__ float red[256];
    const int tid = threadIdx.x;
    float ls = 0.f;
    for (int r = tid; r < BT; r += 256) ls += lossrow[r];
    red[tid] = ls; __syncthreads();
    for (int st = 128; st > 0; st >>= 1) { if (tid < st) red[tid] += red[tid + st]; __syncthreads(); }
    float loss = -red[0] / (float)BT;
    for (long i = tid; i < count; i += 256) dst[i] = loss;
}

// ---------------------------------------------------------------------------
// Host orchestration
// ---------------------------------------------------------------------------
extern "C" void kernel_launch(void* const* d_in, const int* in_sizes, int n_in,
                              void* d_out, int out_size)
{
    const int* idx = (const int*)d_in[0];
    const int* tgt = (const int*)d_in[1];
    const float* tok  = (const float*)d_in[2];
    const float* pos  = (const float*)d_in[3];
    const float* Wq   = (const float*)d_in[4];
    const float* bq   = (const float*)d_in[5];
    const float* Wk   = (const float*)d_in[6];
    const float* bk   = (const float*)d_in[7];
    const float* Wv   = (const float*)d_in[8];
    const float* bv   = (const float*)d_in[9];
    const float* Wo   = (const float*)d_in[10];
    const float* bo   = (const float*)d_in[11];
    const float* w1   = (const float*)d_in[12];
    const float* b1   = (const float*)d_in[13];
    const float* w2   = (const float*)d_in[14];
    const float* b2   = (const float*)d_in[15];
    const float* ln1s = (const float*)d_in[16];
    const float* ln1b = (const float*)d_in[17];
    const float* ln2s = (const float*)d_in[18];
    const float* ln2b = (const float*)d_in[19];
    const float* lnfs = (const float*)d_in[20];
    const float* lnfb = (const float*)d_in[21];
    const float* Wlm  = (const float*)d_in[22];
    const float* blm  = (const float*)d_in[23];
    float* out = (float*)d_out;

    float *x, *h, *q, *k, *v, *o, *attn, *mlp, *logits, *lrow;
    cudaGetSymbolAddress((void**)&x,      g_x);
    cudaGetSymbolAddress((void**)&h,      g_h);
    cudaGetSymbolAddress((void**)&q,      g_q);
    cudaGetSymbolAddress((void**)&k,      g_k);
    cudaGetSymbolAddress((void**)&v,      g_v);
    cudaGetSymbolAddress((void**)&o,      g_o);
    cudaGetSymbolAddress((void**)&attn,   g_attn);
    cudaGetSymbolAddress((void**)&mlp,    g_mlp);
    cudaGetSymbolAddress((void**)&logits, g_logits);
    cudaGetSymbolAddress((void**)&lrow,   g_lossrow);

    static int smem_set = 0;
    if (!smem_set) {
        cudaFuncSetAttribute(gemm128, cudaFuncAttributeMaxDynamicSharedMemorySize, SMEM_BYTES);
        cudaFuncSetAttribute(gemm_qkv, cudaFuncAttributeMaxDynamicSharedMemorySize, SMEM_BYTES);
        smem_set = 1;
    }

    const long BTV = (long)BT * VV;
    const long osz = (long)(unsigned)out_size;
    float* logits_dst = (osz >= BTV) ? out : logits;

    embed_kernel<<<(BT * EE + 255) / 256, 256>>>(idx, tok, pos, x);

    dim3 gE(EE / 128, BT / 128, 1);
    dim3 gQKV(EE / 128, BT / 128, 3);
    dim3 gF(FF / 128, BT / 128, 1);
    dim3 gAV(1, TT / 128, BB * HH);
    dim3 gLM(VV / 128, BT / 128, 1);

    for (int l = 0; l < LL; l++) {
        long wofs = (long)l * EE * EE;
        ln_kernel<<<BT, 256>>>(x, ln1s + l * EE, ln1b + l * EE, h);
        gemm_qkv<<<gQKV, 256, SMEM_BYTES>>>(h, Wq + wofs, Wk + wofs, Wv + wofs,
                                            q, k, v, bq + l * EE, bk + l * EE, bv + l * EE);

        attn_scores_kernel<<<dim3(TT, HH, BB), 256>>>(q, k, attn);

        gemm128<<<gAV, 256, SMEM_BYTES>>>(attn, v, o, nullptr, TT, HD, TT, TT, EE, EE,
                              (long)TT * TT, (long)TT * EE, HD, (long)TT * EE, HD, HH, 0);

        gemm128<<<gE, 256, SMEM_BYTES>>>(o, Wo + wofs, x, bo + l * EE, BT, EE, EE, EE, EE, EE,
                             0, 0, 0, 0, 0, 1, FLAG_ACCUM);

        ln_kernel<<<BT, 256>>>(x, ln2s + l * EE, ln2b + l * EE, h);
        gemm128<<<gF, 256, SMEM_BYTES>>>(h, w1 + (long)l * EE * FF, mlp, b1 + (long)l * FF,
                             BT, FF, EE, EE, FF, FF, 0, 0, 0, 0, 0, 1, FLAG_RELU);
        gemm128<<<gE, 256, SMEM_BYTES>>>(mlp, w2 + (long)l * FF * EE, x, b2 + l * EE,
                             BT, EE, FF, FF, EE, EE, 0, 0, 0, 0, 0, 1, FLAG_ACCUM);
    }

    ln_kernel<<<BT, 256>>>(x, lnfs, lnfb, h);
    gemm128<<<gLM, 256, SMEM_BYTES>>>(h, Wlm, logits_dst, blm, BT, VV, EE, EE, VV, VV, 0, 0, 0, 0, 0, 1, 0);

    lossrow_kernel<<<BT, 256>>>(logits_dst, tgt, lrow);
    if (osz > BTV) {
        lossfinal_kernel<<<1, 256>>>(lrow, out + BTV, osz - BTV);
    } else if (osz < BTV) {
        lossfinal_kernel<<<1, 256>>>(lrow, out, osz);
    }
}

// round 13
// speedup vs baseline: 2.5342x; 1.0848x over previous
#include <cuda_runtime.h>
#include <math.h>
#include <stdint.h>

// Problem dims
#define BB 4
#define TT 1024
#define EE 768
#define HH 6
#define HD 128
#define LL 6
#define VV 32000
#define BT (BB*TT)   // 4096
#define FF (4*EE)    // 3072

// Scratch (device globals -- no runtime allocation allowed)
__device__ float g_x[BT*EE];
__device__ float g_h[BT*EE];
__device__ float g_q[BT*EE];
__device__ float g_k[BT*EE];
__device__ float g_v[BT*EE];
__device__ float g_o[BT*EE];
__device__ float g_attn[(long)BB*HH*TT*TT];
__device__ float g_mlp[BT*FF];
__device__ float g_logits[(long)BT*VV];
__device__ float g_lossrow[BT];

#define FLAG_RELU  1
#define FLAG_ACCUM 2

#define LDSTRIDE 136   // 136 mod 32 = 8 -> fragment loads are bank-conflict-free

__device__ __forceinline__ float to_tf32(float x) {
    float r;
    asm("cvt.rna.tf32.f32 %0, %1;" : "=f"(r) : "f"(x));
    return r;
}

__device__ __forceinline__ void mma_tf32(float c[4], uint32_t a0, uint32_t a1,
                                         uint32_t a2, uint32_t a3,
                                         uint32_t b0, uint32_t b1) {
    asm volatile(
        "mma.sync.aligned.m16n8k8.row.col.f32.tf32.tf32.f32 "
        "{%0,%1,%2,%3}, {%4,%5,%6,%7}, {%8,%9}, {%0,%1,%2,%3};\n"
        : "+f"(c[0]), "+f"(c[1]), "+f"(c[2]), "+f"(c[3])
        : "r"(a0), "r"(a1), "r"(a2), "r"(a3), "r"(b0), "r"(b1));
}

// ---------------------------------------------------------------------------
// TF32 tensor-core GEMM core: 128x128 block tile, K-step 32, single-buffer
// smem (static, 34.8KB) with conflict-free fragment loads; 2 CTAs/SM overlap
// hides the sync/latency bubbles. 8 warps 2(M)x4(N), warp tile 64x32 via
// 4x4 m16n8k8. Requires M%128==0, N%128==0 (per tile), K%32==0.
// ---------------------------------------------------------------------------
struct GemmSmem {
    float As[32][LDSTRIDE];
    float Bs[32][LDSTRIDE];
};

__device__ __forceinline__ void gemm_core(
    const float* __restrict__ Ab, const float* __restrict__ Bb,
    float* __restrict__ Cb, const float* __restrict__ bias,
    int K, int lda, int ldb, int ldc, int m0, int n0, int flags, GemmSmem& sm)
{
    const int tid  = threadIdx.x;
    const int lane = tid & 31;
    const int wid  = tid >> 5;
    const int warp_m = wid & 1;
    const int warp_n = wid >> 1;

    const int a_r  = tid >> 1;            // A row 0..127
    const int a_q0 = (tid & 1) * 16;      // k offset 0/16
    const int b_k  = tid >> 3;            // k 0..31
    const int b_n0 = (tid & 7) * 16;      // n offset

    const int fr = lane >> 2;
    const int fc = lane & 3;

    float acc[4][4][4];
    #pragma unroll
    for (int i = 0; i < 4; i++)
        #pragma unroll
        for (int j = 0; j < 4; j++)
            #pragma unroll
            for (int u = 0; u < 4; u++) acc[i][j][u] = 0.f;

    for (int kt = 0; kt < K; kt += 32) {
        float4 av[4], bv[4];
        #pragma unroll
        for (int i = 0; i < 4; i++) {
            av[i] = *(const float4*)&Ab[(long)(m0 + a_r) * lda + kt + a_q0 + i * 4];
            bv[i] = *(const float4*)&Bb[(long)(kt + b_k) * ldb + n0 + b_n0 + i * 4];
        }
        __syncthreads();
        #pragma unroll
        for (int i = 0; i < 4; i++) {
            sm.As[a_q0 + i*4 + 0][a_r] = to_tf32(av[i].x);
            sm.As[a_q0 + i*4 + 1][a_r] = to_tf32(av[i].y);
            sm.As[a_q0 + i*4 + 2][a_r] = to_tf32(av[i].z);
            sm.As[a_q0 + i*4 + 3][a_r] = to_tf32(av[i].w);
            float4 t = make_float4(to_tf32(bv[i].x), to_tf32(bv[i].y),
                                   to_tf32(bv[i].z), to_tf32(bv[i].w));
            *(float4*)&sm.Bs[b_k][b_n0 + i*4] = t;
        }
        __syncthreads();

        #pragma unroll
        for (int ks = 0; ks < 4; ks++) {
            const int kk = ks * 8;
            uint32_t afr[4][4];
            #pragma unroll
            for (int mt = 0; mt < 4; mt++) {
                int mb = warp_m * 64 + mt * 16 + fr;
                afr[mt][0] = __float_as_uint(sm.As[kk + fc    ][mb]);
                afr[mt][1] = __float_as_uint(sm.As[kk + fc    ][mb + 8]);
                afr[mt][2] = __float_as_uint(sm.As[kk + fc + 4][mb]);
                afr[mt][3] = __float_as_uint(sm.As[kk + fc + 4][mb + 8]);
            }
            uint32_t bfr[4][2];
            #pragma unroll
            for (int nt = 0; nt < 4; nt++) {
                int nb = warp_n * 32 + nt * 8 + fr;
                bfr[nt][0] = __float_as_uint(sm.Bs[kk + fc    ][nb]);
                bfr[nt][1] = __float_as_uint(sm.Bs[kk + fc + 4][nb]);
            }
            #pragma unroll
            for (int mt = 0; mt < 4; mt++)
                #pragma unroll
                for (int nt = 0; nt < 4; nt++)
                    mma_tf32(acc[mt][nt], afr[mt][0], afr[mt][1], afr[mt][2], afr[mt][3],
                             bfr[nt][0], bfr[nt][1]);
        }
    }

    // Epilogue
    #pragma unroll
    for (int nt = 0; nt < 4; nt++) {
        const int col = n0 + warp_n * 32 + nt * 8 + fc * 2;
        float bj0 = bias ? bias[col]     : 0.f;
        float bj1 = bias ? bias[col + 1] : 0.f;
        #pragma unroll
        for (int mt = 0; mt < 4; mt++) {
            const int row = m0 + warp_m * 64 + mt * 16 + fr;
            #pragma unroll
            for (int half = 0; half < 2; half++) {
                long base = (long)(row + half * 8) * ldc + col;
                float v0 = acc[mt][nt][half * 2 + 0] + bj0;
                float v1 = acc[mt][nt][half * 2 + 1] + bj1;
                if (flags & FLAG_ACCUM) { v0 += Cb[base]; v1 += Cb[base + 1]; }
                if (flags & FLAG_RELU)  { v0 = fmaxf(v0, 0.f); v1 = fmaxf(v1, 0.f); }
                Cb[base]     = v0;
                Cb[base + 1] = v1;
            }
        }
    }
}

// Generic strided/batched wrapper
__global__ __launch_bounds__(256, 2) void gemm128(
    const float* __restrict__ A, const float* __restrict__ B,
    float* __restrict__ C, const float* __restrict__ bias,
    int M, int N, int K, int lda, int ldb, int ldc,
    long sA, long sBo, long sBi, long sCo, long sCi, int zdiv, int flags)
{
    __shared__ GemmSmem sm;
    const int z = blockIdx.z;
    const float* Ab = A + (long)z * sA;
    const float* Bb = B + (long)(z / zdiv) * sBo + (long)(z % zdiv) * sBi;
    float*       Cb = C + (long)(z / zdiv) * sCo + (long)(z % zdiv) * sCi;
    gemm_core(Ab, Bb, Cb, bias, K, lda, ldb, ldc,
              blockIdx.y * 128, blockIdx.x * 128, flags, sm);
}

// Fused QKV: z in {0,1,2} selects weight/output set (wave packing)
__global__ __launch_bounds__(256, 2) void gemm_qkv(
    const float* __restrict__ A,
    const float* __restrict__ B0, const float* __restrict__ B1, const float* __restrict__ B2,
    float* __restrict__ C0, float* __restrict__ C1, float* __restrict__ C2,
    const float* __restrict__ bi0, const float* __restrict__ bi1, const float* __restrict__ bi2)
{
    __shared__ GemmSmem sm;
    const int z = blockIdx.z;
    const float* Bb = (z == 0) ? B0 : (z == 1) ? B1 : B2;
    float*       Cb = (z == 0) ? C0 : (z == 1) ? C1 : C2;
    const float* bi = (z == 0) ? bi0 : (z == 1) ? bi1 : bi2;
    gemm_core(A, Bb, Cb, bi, EE, EE, EE, EE,
              blockIdx.y * 128, blockIdx.x * 128, 0, sm);
}

// ---------------------------------------------------------------------------
// Embedding
// ---------------------------------------------------------------------------
__global__ void embed_kernel(const int* __restrict__ idx,
                             const float* __restrict__ tok,
                             const float* __restrict__ pos,
                             float* __restrict__ x)
{
    long i = (long)blockIdx.x * 256 + threadIdx.x;
    if (i >= (long)BT * EE) return;
    int row = (int)(i / EE);
    int col = (int)(i % EE);
    long tkn = idx[row];
    tkn = ((tkn % VV) + VV) % VV;
    x[i] = tok[tkn * EE + col] + pos[(long)(row % TT) * EE + col];
}

// ---------------------------------------------------------------------------
// LayerNorm
// ---------------------------------------------------------------------------
__global__ __launch_bounds__(256) void ln_kernel(
    const float* __restrict__ x, const float* __restrict__ s,
    const float* __restrict__ b, float* __restrict__ o)
{
    __shared__ float red[256];
    const int row = blockIdx.x;
    const int tid = threadIdx.x;
    const float* xr = x + (long)row * EE;

    float ls = 0.f;
    for (int c = tid; c < EE; c += 256) ls += xr[c];
    red[tid] = ls; __syncthreads();
    for (int st = 128; st > 0; st >>= 1) { if (tid < st) red[tid] += red[tid + st]; __syncthreads(); }
    float mu = red[0] / EE;
    __syncthreads();

    float lv = 0.f;
    for (int c = tid; c < EE; c += 256) { float d = xr[c] - mu; lv += d * d; }
    red[tid] = lv; __syncthreads();
    for (int st = 128; st > 0; st >>= 1) { if (tid < st) red[tid] += red[tid + st]; __syncthreads(); }
    float rs = rsqrtf(red[0] / EE + 1e-5f);

    float* orow = o + (long)row * EE;
    for (int c = tid; c < EE; c += 256)
        orow[c] = (xr[c] - mu) * rs * s[c] + b[c];
}

// ---------------------------------------------------------------------------
// Attention scores + causal softmax
// ---------------------------------------------------------------------------
__global__ __launch_bounds__(256) void attn_scores_kernel(
    const float* __restrict__ Q, const float* __restrict__ Km, float* __restrict__ P)
{
    __shared__ float4 qs[HD / 4];
    __shared__ float red[256];
    const int qi = blockIdx.x, h = blockIdx.y, b = blockIdx.z;
    const int tid = threadIdx.x;
    const float scale = 0.08838834764831845f;

    const float* qrow = Q + ((long)(b * TT + qi)) * EE + h * HD;
    if (tid < HD / 4) qs[tid] = ((const float4*)qrow)[tid];
    __syncthreads();

    float sc[4];
    float lm = -1e30f;
    #pragma unroll
    for (int j = 0; j < 4; j++) {
        int key = tid + j * 256;
        float d = -1e30f;
        if (key <= qi) {
            const float4* kr = (const float4*)(Km + ((long)(b * TT + key)) * EE + h * HD);
            float a = 0.f;
            #pragma unroll
            for (int u = 0; u < HD / 4; u++) {
                float4 kv = kr[u]; float4 qv = qs[u];
                a += kv.x * qv.x + kv.y * qv.y + kv.z * qv.z + kv.w * qv.w;
            }
            d = a * scale;
            lm = fmaxf(lm, d);
        }
        sc[j] = d;
    }
    red[tid] = lm; __syncthreads();
    for (int st = 128; st > 0; st >>= 1) { if (tid < st) red[tid] = fmaxf(red[tid], red[tid + st]); __syncthreads(); }
    float m = red[0];
    __syncthreads();

    float ssum = 0.f;
    #pragma unroll
    for (int j = 0; j < 4; j++) {
        if (sc[j] > -1e29f) { sc[j] = expf(sc[j] - m); ssum += sc[j]; }
        else sc[j] = 0.f;
    }
    red[tid] = ssum; __syncthreads();
    for (int st = 128; st > 0; st >>= 1) { if (tid < st) red[tid] += red[tid + st]; __syncthreads(); }
    float sinv = 1.f / red[0];

    float* prow = P + (((long)(b * HH + h) * TT + qi) * TT);
    #pragma unroll
    for (int j = 0; j < 4; j++)
        prow[tid + j * 256] = sc[j] * sinv;
}

// ---------------------------------------------------------------------------
// Loss
// ---------------------------------------------------------------------------
__global__ __launch_bounds__(256) void lossrow_kernel(
    const float* __restrict__ logits, const int* __restrict__ tgt,
    float* __restrict__ lossrow)
{
    __shared__ float red[256];
    const int row = blockIdx.x;
    const int tid = threadIdx.x;
    const float* lr = logits + (long)row * VV;

    float lm = -1e30f;
    for (int c = tid; c < VV; c += 256) lm = fmaxf(lm, lr[c]);
    red[tid] = lm; __syncthreads();
    for (int st = 128; st > 0; st >>= 1) { if (tid < st) red[tid] = fmaxf(red[tid], red[tid + st]); __syncthreads(); }
    float m = red[0];
    __syncthreads();

    float ls = 0.f;
    for (int c = tid; c < VV; c += 256) ls += expf(lr[c] - m);
    red[tid] = ls; __syncthreads();
    for (int st = 128; st > 0; st >>= 1) { if (tid < st) red[tid] += red[tid + st]; __syncthreads(); }

    if (tid == 0) {
        long t = tgt[row];
        t = ((t % VV) + VV) % VV;
        lossrow[row] = lr[t] - m - logf(red[0]);
    }
}

__global__ __launch_bounds__(256) void lossfinal_kernel(
    const float* __restrict__ lossrow, float* __restrict__ dst, long count)
{
    __shared__ float red[256];
    const int tid = threadIdx.x;
    float ls = 0.f;
    for (int r = tid; r < BT; r += 256) ls += lossrow[r];
    red[tid] = ls; __syncthreads();
    for (int st = 128; st > 0; st >>= 1) { if (tid < st) red[tid] += red[tid + st]; __syncthreads(); }
    float loss = -red[0] / (float)BT;
    for (long i = tid; i < count; i += 256) dst[i] = loss;
}

// ---------------------------------------------------------------------------
// Host orchestration
// ---------------------------------------------------------------------------
extern "C" void kernel_launch(void* const* d_in, const int* in_sizes, int n_in,
                              void* d_out, int out_size)
{
    const int* idx = (const int*)d_in[0];
    const int* tgt = (const int*)d_in[1];
    const float* tok  = (const float*)d_in[2];
    const float* pos  = (const float*)d_in[3];
    const float* Wq   = (const float*)d_in[4];
    const float* bq   = (const float*)d_in[5];
    const float* Wk   = (const float*)d_in[6];
    const float* bk   = (const float*)d_in[7];
    const float* Wv   = (const float*)d_in[8];
    const float* bv   = (const float*)d_in[9];
    const float* Wo   = (const float*)d_in[10];
    const float* bo   = (const float*)d_in[11];
    const float* w1   = (const float*)d_in[12];
    const float* b1   = (const float*)d_in[13];
    const float* w2   = (const float*)d_in[14];
    const float* b2   = (const float*)d_in[15];
    const float* ln1s = (const float*)d_in[16];
    const float* ln1b = (const float*)d_in[17];
    const float* ln2s = (const float*)d_in[18];
    const float* ln2b = (const float*)d_in[19];
    const float* lnfs = (const float*)d_in[20];
    const float* lnfb = (const float*)d_in[21];
    const float* Wlm  = (const float*)d_in[22];
    const float* blm  = (const float*)d_in[23];
    float* out = (float*)d_out;

    float *x, *h, *q, *k, *v, *o, *attn, *mlp, *logits, *lrow;
    cudaGetSymbolAddress((void**)&x,      g_x);
    cudaGetSymbolAddress((void**)&h,      g_h);
    cudaGetSymbolAddress((void**)&q,      g_q);
    cudaGetSymbolAddress((void**)&k,      g_k);
    cudaGetSymbolAddress((void**)&v,      g_v);
    cudaGetSymbolAddress((void**)&o,      g_o);
    cudaGetSymbolAddress((void**)&attn,   g_attn);
    cudaGetSymbolAddress((void**)&mlp,    g_mlp);
    cudaGetSymbolAddress((void**)&logits, g_logits);
    cudaGetSymbolAddress((void**)&lrow,   g_lossrow);

    const long BTV = (long)BT * VV;
    const long osz = (long)(unsigned)out_size;
    float* logits_dst = (osz >= BTV) ? out : logits;

    embed_kernel<<<(BT * EE + 255) / 256, 256>>>(idx, tok, pos, x);

    dim3 gE(EE / 128, BT / 128, 1);
    dim3 gQKV(EE / 128, BT / 128, 3);
    dim3 gF(FF / 128, BT / 128, 1);
    dim3 gAV(1, TT / 128, BB * HH);
    dim3 gLM(VV / 128, BT / 128, 1);

    for (int l = 0; l < LL; l++) {
        long wofs = (long)l * EE * EE;
        ln_kernel<<<BT, 256>>>(x, ln1s + l * EE, ln1b + l * EE, h);
        gemm_qkv<<<gQKV, 256>>>(h, Wq + wofs, Wk + wofs, Wv + wofs,
                                q, k, v, bq + l * EE, bk + l * EE, bv + l * EE);

        attn_scores_kernel<<<dim3(TT, HH, BB), 256>>>(q, k, attn);

        gemm128<<<gAV, 256>>>(attn, v, o, nullptr, TT, HD, TT, TT, EE, EE,
                              (long)TT * TT, (long)TT * EE, HD, (long)TT * EE, HD, HH, 0);

        gemm128<<<gE, 256>>>(o, Wo + wofs, x, bo + l * EE, BT, EE, EE, EE, EE, EE,
                             0, 0, 0, 0, 0, 1, FLAG_ACCUM);

        ln_kernel<<<BT, 256>>>(x, ln2s + l * EE, ln2b + l * EE, h);
        gemm128<<<gF, 256>>>(h, w1 + (long)l * EE * FF, mlp, b1 + (long)l * FF,
                             BT, FF, EE, EE, FF, FF, 0, 0, 0, 0, 0, 1, FLAG_RELU);
        gemm128<<<gE, 256>>>(mlp, w2 + (long)l * FF * EE, x, b2 + l * EE,
                             BT, EE, FF, FF, EE, EE, 0, 0, 0, 0, 0, 1, FLAG_ACCUM);
    }

    ln_kernel<<<BT, 256>>>(x, lnfs, lnfb, h);
    gemm128<<<gLM, 256>>>(h, Wlm, logits_dst, blm, BT, VV, EE, EE, VV, VV, 0, 0, 0, 0, 0, 1, 0);

    lossrow_kernel<<<BT, 256>>>(logits_dst, tgt, lrow);
    if (osz > BTV) {
        lossfinal_kernel<<<1, 256>>>(lrow, out + BTV, osz - BTV);
    } else if (osz < BTV) {
        lossfinal_kernel<<<1, 256>>>(lrow, out, osz);
    }
}

// round 15
// speedup vs baseline: 3.0973x; 1.2222x over previous
#include <cuda_runtime.h>
#include <cuda_fp16.h>
#include <math.h>
#include <stdint.h>

// Problem dims
#define BB 4
#define TT 1024
#define EE 768
#define HH 6
#define HD 128
#define LL 6
#define VV 32000
#define BT (BB*TT)   // 4096
#define FF (4*EE)    // 3072

// Scratch (device globals -- no runtime allocation allowed)
__device__ float g_x[BT*EE];
__device__ float g_h[BT*EE];
__device__ float g_q[BT*EE];
__device__ float g_k[BT*EE];
__device__ float g_v[BT*EE];
__device__ float g_o[BT*EE];
__device__ float g_attn[(long)BB*HH*TT*TT];
__device__ float g_mlp[BT*FF];
__device__ float g_logits[(long)BT*VV];
__device__ float g_lossrow[BT];

#define FLAG_RELU  1
#define FLAG_ACCUM 2

#define K2STRIDE 136   // uint32 units; 136 mod 32 = 8 -> fragment loads conflict-free

__device__ __forceinline__ uint32_t packh2(float lo, float hi) {
    __half2 h = __floats2half2_rn(lo, hi);   // .x = lo (low half)
    return *(uint32_t*)&h;
}

__device__ __forceinline__ void mma_f16(float c[4], uint32_t a0, uint32_t a1,
                                        uint32_t a2, uint32_t a3,
                                        uint32_t b0, uint32_t b1) {
    asm volatile(
        "mma.sync.aligned.m16n8k16.row.col.f32.f16.f16.f32 "
        "{%0,%1,%2,%3}, {%4,%5,%6,%7}, {%8,%9}, {%0,%1,%2,%3};\n"
        : "+f"(c[0]), "+f"(c[1]), "+f"(c[2]), "+f"(c[3])
        : "r"(a0), "r"(a1), "r"(a2), "r"(a3), "r"(b0), "r"(b1));
}

// ---------------------------------------------------------------------------
// FP16 tensor-core GEMM core: 128x128 block tile, K-step 32, double-buffered
// smem (2x17.4KB), one __syncthreads per K-iter, 2 CTAs/SM.
// Smem holds half2 pairs along k: As[s][k2][m], Bs[s][k2][n] (uint32 each).
// 8 warps 2(M)x4(N); warp tile 64x32 via 4x4 m16n8k16.
// Requires M,N tile-aligned, K%32==0.
// ---------------------------------------------------------------------------
struct GemmSmem {
    uint32_t As[2][16][K2STRIDE];
    uint32_t Bs[2][16][K2STRIDE];
};

__device__ __forceinline__ void gemm_core(
    const float* __restrict__ Ab, const float* __restrict__ Bb,
    float* __restrict__ Cb, const float* __restrict__ bias,
    int K, int lda, int ldb, int ldc, int m0, int n0, int flags, GemmSmem& sm)
{
    const int tid  = threadIdx.x;
    const int lane = tid & 31;
    const int wid  = tid >> 5;
    const int warp_m = wid & 1;
    const int warp_n = wid >> 1;

    // A staging: 2 threads per row, each covers 16 k (8 k2-pairs)
    const int a_r  = tid >> 1;            // row 0..127
    const int a_k2 = (tid & 1) * 8;       // k2 offset 0/8 (k offset 0/16)
    // B staging: thread -> (k2, 8-wide n group)
    const int b_k2 = tid >> 4;            // 0..15
    const int b_ng = (tid & 15) * 8;      // n offset

    const int fr = lane >> 2;   // 0..7
    const int fc = lane & 3;    // 0..3

    float acc[4][4][4];
    #pragma unroll
    for (int i = 0; i < 4; i++)
        #pragma unroll
        for (int j = 0; j < 4; j++)
            #pragma unroll
            for (int u = 0; u < 4; u++) acc[i][j][u] = 0.f;

    float4 av[4];          // A: 16 k values for row a_r
    float4 be0, be1, bo0, bo1;  // B: rows 2*b_k2 (even) and +1 (odd), 8 n each

    // ---- Prologue: fetch + stage buffer 0 ----
    #pragma unroll
    for (int i = 0; i < 4; i++)
        av[i] = *(const float4*)&Ab[(long)(m0 + a_r) * lda + a_k2 * 2 + i * 4];
    {
        const float* br0 = &Bb[(long)(2 * b_k2) * ldb + n0 + b_ng];
        const float* br1 = br0 + ldb;
        be0 = *(const float4*)br0; be1 = *(const float4*)(br0 + 4);
        bo0 = *(const float4*)br1; bo1 = *(const float4*)(br1 + 4);
    }
    #pragma unroll
    for (int i = 0; i < 4; i++) {
        sm.As[0][a_k2 + 2*i    ][a_r] = packh2(av[i].x, av[i].y);
        sm.As[0][a_k2 + 2*i + 1][a_r] = packh2(av[i].z, av[i].w);
    }
    {
        uint4 p0, p1;
        p0.x = packh2(be0.x, bo0.x); p0.y = packh2(be0.y, bo0.y);
        p0.z = packh2(be0.z, bo0.z); p0.w = packh2(be0.w, bo0.w);
        p1.x = packh2(be1.x, bo1.x); p1.y = packh2(be1.y, bo1.y);
        p1.z = packh2(be1.z, bo1.z); p1.w = packh2(be1.w, bo1.w);
        *(uint4*)&sm.Bs[0][b_k2][b_ng]     = p0;
        *(uint4*)&sm.Bs[0][b_k2][b_ng + 4] = p1;
    }
    __syncthreads();

    int s = 0;
    for (int kt = 0; kt < K; kt += 32) {
        const bool has_next = (kt + 32) < K;
        if (has_next) {
            #pragma unroll
            for (int i = 0; i < 4; i++)
                av[i] = *(const float4*)&Ab[(long)(m0 + a_r) * lda + kt + 32 + a_k2 * 2 + i * 4];
            const float* br0 = &Bb[(long)(kt + 32 + 2 * b_k2) * ldb + n0 + b_ng];
            const float* br1 = br0 + ldb;
            be0 = *(const float4*)br0; be1 = *(const float4*)(br0 + 4);
            bo0 = *(const float4*)br1; bo1 = *(const float4*)(br1 + 4);
        }

        // ---- Compute on stage s: 2 k16 steps ----
        const uint32_t (*As_s)[K2STRIDE] = sm.As[s];
        const uint32_t (*Bs_s)[K2STRIDE] = sm.Bs[s];
        #pragma unroll
        for (int ks = 0; ks < 2; ks++) {
            const int kk2 = ks * 8;
            uint32_t afr[4][4];
            #pragma unroll
            for (int mt = 0; mt < 4; mt++) {
                int mb = warp_m * 64 + mt * 16 + fr;
                afr[mt][0] = As_s[kk2 + fc    ][mb];
                afr[mt][1] = As_s[kk2 + fc    ][mb + 8];
                afr[mt][2] = As_s[kk2 + 4 + fc][mb];
                afr[mt][3] = As_s[kk2 + 4 + fc][mb + 8];
            }
            uint32_t bfr[4][2];
            #pragma unroll
            for (int nt = 0; nt < 4; nt++) {
                int nb = warp_n * 32 + nt * 8 + fr;
                bfr[nt][0] = Bs_s[kk2 + fc    ][nb];
                bfr[nt][1] = Bs_s[kk2 + 4 + fc][nb];
            }
            #pragma unroll
            for (int mt = 0; mt < 4; mt++)
                #pragma unroll
                for (int nt = 0; nt < 4; nt++)
                    mma_f16(acc[mt][nt], afr[mt][0], afr[mt][1], afr[mt][2], afr[mt][3],
                            bfr[nt][0], bfr[nt][1]);
        }

        if (has_next) {
            const int ns = s ^ 1;
            #pragma unroll
            for (int i = 0; i < 4; i++) {
                sm.As[ns][a_k2 + 2*i    ][a_r] = packh2(av[i].x, av[i].y);
                sm.As[ns][a_k2 + 2*i + 1][a_r] = packh2(av[i].z, av[i].w);
            }
            uint4 p0, p1;
            p0.x = packh2(be0.x, bo0.x); p0.y = packh2(be0.y, bo0.y);
            p0.z = packh2(be0.z, bo0.z); p0.w = packh2(be0.w, bo0.w);
            p1.x = packh2(be1.x, bo1.x); p1.y = packh2(be1.y, bo1.y);
            p1.z = packh2(be1.z, bo1.z); p1.w = packh2(be1.w, bo1.w);
            *(uint4*)&sm.Bs[ns][b_k2][b_ng]     = p0;
            *(uint4*)&sm.Bs[ns][b_k2][b_ng + 4] = p1;
            __syncthreads();
            s = ns;
        }
    }

    // ---- Epilogue ----
    #pragma unroll
    for (int nt = 0; nt < 4; nt++) {
        const int col = n0 + warp_n * 32 + nt * 8 + fc * 2;
        float bj0 = bias ? bias[col]     : 0.f;
        float bj1 = bias ? bias[col + 1] : 0.f;
        #pragma unroll
        for (int mt = 0; mt < 4; mt++) {
            const int row = m0 + warp_m * 64 + mt * 16 + fr;
            #pragma unroll
            for (int half = 0; half < 2; half++) {
                long base = (long)(row + half * 8) * ldc + col;
                float v0 = acc[mt][nt][half * 2 + 0] + bj0;
                float v1 = acc[mt][nt][half * 2 + 1] + bj1;
                if (flags & FLAG_ACCUM) { v0 += Cb[base]; v1 += Cb[base + 1]; }
                if (flags & FLAG_RELU)  { v0 = fmaxf(v0, 0.f); v1 = fmaxf(v1, 0.f); }
                Cb[base]     = v0;
                Cb[base + 1] = v1;
            }
        }
    }
}

// Generic strided/batched wrapper
__global__ __launch_bounds__(256, 2) void gemm128(
    const float* __restrict__ A, const float* __restrict__ B,
    float* __restrict__ C, const float* __restrict__ bias,
    int M, int N, int K, int lda, int ldb, int ldc,
    long sA, long sBo, long sBi, long sCo, long sCi, int zdiv, int flags)
{
    __shared__ GemmSmem sm;
    const int z = blockIdx.z;
    const float* Ab = A + (long)z * sA;
    const float* Bb = B + (long)(z / zdiv) * sBo + (long)(z % zdiv) * sBi;
    float*       Cb = C + (long)(z / zdiv) * sCo + (long)(z % zdiv) * sCi;
    gemm_core(Ab, Bb, Cb, bias, K, lda, ldb, ldc,
              blockIdx.y * 128, blockIdx.x * 128, flags, sm);
}

// Fused QKV: z in {0,1,2} selects weight/output set (wave packing)
__global__ __launch_bounds__(256, 2) void gemm_qkv(
    const float* __restrict__ A,
    const float* __restrict__ B0, const float* __restrict__ B1, const float* __restrict__ B2,
    float* __restrict__ C0, float* __restrict__ C1, float* __restrict__ C2,
    const float* __restrict__ bi0, const float* __restrict__ bi1, const float* __restrict__ bi2)
{
    __shared__ GemmSmem sm;
    const int z = blockIdx.z;
    const float* Bb = (z == 0) ? B0 : (z == 1) ? B1 : B2;
    float*       Cb = (z == 0) ? C0 : (z == 1) ? C1 : C2;
    const float* bi = (z == 0) ? bi0 : (z == 1) ? bi1 : bi2;
    gemm_core(A, Bb, Cb, bi, EE, EE, EE, EE,
              blockIdx.y * 128, blockIdx.x * 128, 0, sm);
}

// ---------------------------------------------------------------------------
// Embedding
// ---------------------------------------------------------------------------
__global__ void embed_kernel(const int* __restrict__ idx,
                             const float* __restrict__ tok,
                             const float* __restrict__ pos,
                             float* __restrict__ x)
{
    long i = (long)blockIdx.x * 256 + threadIdx.x;
    if (i >= (long)BT * EE) return;
    int row = (int)(i / EE);
    int col = (int)(i % EE);
    long tkn = idx[row];
    tkn = ((tkn % VV) + VV) % VV;
    x[i] = tok[tkn * EE + col] + pos[(long)(row % TT) * EE + col];
}

// ---------------------------------------------------------------------------
// LayerNorm
// ---------------------------------------------------------------------------
__global__ __launch_bounds__(256) void ln_kernel(
    const float* __restrict__ x, const float* __restrict__ s,
    const float* __restrict__ b, float* __restrict__ o)
{
    __shared__ float red[256];
    const int row = blockIdx.x;
    const int tid = threadIdx.x;
    const float* xr = x + (long)row * EE;

    float ls = 0.f;
    for (int c = tid; c < EE; c += 256) ls += xr[c];
    red[tid] = ls; __syncthreads();
    for (int st = 128; st > 0; st >>= 1) { if (tid < st) red[tid] += red[tid + st]; __syncthreads(); }
    float mu = red[0] / EE;
    __syncthreads();

    float lv = 0.f;
    for (int c = tid; c < EE; c += 256) { float d = xr[c] - mu; lv += d * d; }
    red[tid] = lv; __syncthreads();
    for (int st = 128; st > 0; st >>= 1) { if (tid < st) red[tid] += red[tid + st]; __syncthreads(); }
    float rs = rsqrtf(red[0] / EE + 1e-5f);

    float* orow = o + (long)row * EE;
    for (int c = tid; c < EE; c += 256)
        orow[c] = (xr[c] - mu) * rs * s[c] + b[c];
}

// ---------------------------------------------------------------------------
// Attention scores + causal softmax
// ---------------------------------------------------------------------------
__global__ __launch_bounds__(256) void attn_scores_kernel(
    const float* __restrict__ Q, const float* __restrict__ Km, float* __restrict__ P)
{
    __shared__ float4 qs[HD / 4];
    __shared__ float red[256];
    const int qi = blockIdx.x, h = blockIdx.y, b = blockIdx.z;
    const int tid = threadIdx.x;
    const float scale = 0.08838834764831845f;

    const float* qrow = Q + ((long)(b * TT + qi)) * EE + h * HD;
    if (tid < HD / 4) qs[tid] = ((const float4*)qrow)[tid];
    __syncthreads();

    float sc[4];
    float lm = -1e30f;
    #pragma unroll
    for (int j = 0; j < 4; j++) {
        int key = tid + j * 256;
        float d = -1e30f;
        if (key <= qi) {
            const float4* kr = (const float4*)(Km + ((long)(b * TT + key)) * EE + h * HD);
            float a = 0.f;
            #pragma unroll
            for (int u = 0; u < HD / 4; u++) {
                float4 kv = kr[u]; float4 qv = qs[u];
                a += kv.x * qv.x + kv.y * qv.y + kv.z * qv.z + kv.w * qv.w;
            }
            d = a * scale;
            lm = fmaxf(lm, d);
        }
        sc[j] = d;
    }
    red[tid] = lm; __syncthreads();
    for (int st = 128; st > 0; st >>= 1) { if (tid < st) red[tid] = fmaxf(red[tid], red[tid + st]); __syncthreads(); }
    float m = red[0];
    __syncthreads();

    float ssum = 0.f;
    #pragma unroll
    for (int j = 0; j < 4; j++) {
        if (sc[j] > -1e29f) { sc[j] = expf(sc[j] - m); ssum += sc[j]; }
        else sc[j] = 0.f;
    }
    red[tid] = ssum; __syncthreads();
    for (int st = 128; st > 0; st >>= 1) { if (tid < st) red[tid] += red[tid + st]; __syncthreads(); }
    float sinv = 1.f / red[0];

    float* prow = P + (((long)(b * HH + h) * TT + qi) * TT);
    #pragma unroll
    for (int j = 0; j < 4; j++)
        prow[tid + j * 256] = sc[j] * sinv;
}

// ---------------------------------------------------------------------------
// Loss
// ---------------------------------------------------------------------------
__global__ __launch_bounds__(256) void lossrow_kernel(
    const float* __restrict__ logits, const int* __restrict__ tgt,
    float* __restrict__ lossrow)
{
    __shared__ float red[256];
    const int row = blockIdx.x;
    const int tid = threadIdx.x;
    const float* lr = logits + (long)row * VV;

    float lm = -1e30f;
    for (int c = tid; c < VV; c += 256) lm = fmaxf(lm, lr[c]);
    red[tid] = lm; __syncthreads();
    for (int st = 128; st > 0; st >>= 1) { if (tid < st) red[tid] = fmaxf(red[tid], red[tid + st]); __syncthreads(); }
    float m = red[0];
    __syncthreads();

    float ls = 0.f;
    for (int c = tid; c < VV; c += 256) ls += expf(lr[c] - m);
    red[tid] = ls; __syncthreads();
    for (int st = 128; st > 0; st >>= 1) { if (tid < st) red[tid] += red[tid + st]; __syncthreads(); }

    if (tid == 0) {
        long t = tgt[row];
        t = ((t % VV) + VV) % VV;
        lossrow[row] = lr[t] - m - logf(red[0]);
    }
}

__global__ __launch_bounds__(256) void lossfinal_kernel(
    const float* __restrict__ lossrow, float* __restrict__ dst, long count)
{
    __shared__ float red[256];
    const int tid = threadIdx.x;
    float ls = 0.f;
    for (int r = tid; r < BT; r += 256) ls += lossrow[r];
    red[tid] = ls; __syncthreads();
    for (int st = 128; st > 0; st >>= 1) { if (tid < st) red[tid] += red[tid + st]; __syncthreads(); }
    float loss = -red[0] / (float)BT;
    for (long i = tid; i < count; i += 256) dst[i] = loss;
}

// ---------------------------------------------------------------------------
// Host orchestration
// ---------------------------------------------------------------------------
extern "C" void kernel_launch(void* const* d_in, const int* in_sizes, int n_in,
                              void* d_out, int out_size)
{
    const int* idx = (const int*)d_in[0];
    const int* tgt = (const int*)d_in[1];
    const float* tok  = (const float*)d_in[2];
    const float* pos  = (const float*)d_in[3];
    const float* Wq   = (const float*)d_in[4];
    const float* bq   = (const float*)d_in[5];
    const float* Wk   = (const float*)d_in[6];
    const float* bk   = (const float*)d_in[7];
    const float* Wv   = (const float*)d_in[8];
    const float* bv   = (const float*)d_in[9];
    const float* Wo   = (const float*)d_in[10];
    const float* bo   = (const float*)d_in[11];
    const float* w1   = (const float*)d_in[12];
    const float* b1   = (const float*)d_in[13];
    const float* w2   = (const float*)d_in[14];
    const float* b2   = (const float*)d_in[15];
    const float* ln1s = (const float*)d_in[16];
    const float* ln1b = (const float*)d_in[17];
    const float* ln2s = (const float*)d_in[18];
    const float* ln2b = (const float*)d_in[19];
    const float* lnfs = (const float*)d_in[20];
    const float* lnfb = (const float*)d_in[21];
    const float* Wlm  = (const float*)d_in[22];
    const float* blm  = (const float*)d_in[23];
    float* out = (float*)d_out;

    float *x, *h, *q, *k, *v, *o, *attn, *mlp, *logits, *lrow;
    cudaGetSymbolAddress((void**)&x,      g_x);
    cudaGetSymbolAddress((void**)&h,      g_h);
    cudaGetSymbolAddress((void**)&q,      g_q);
    cudaGetSymbolAddress((void**)&k,      g_k);
    cudaGetSymbolAddress((void**)&v,      g_v);
    cudaGetSymbolAddress((void**)&o,      g_o);
    cudaGetSymbolAddress((void**)&attn,   g_attn);
    cudaGetSymbolAddress((void**)&mlp,    g_mlp);
    cudaGetSymbolAddress((void**)&logits, g_logits);
    cudaGetSymbolAddress((void**)&lrow,   g_lossrow);

    const long BTV = (long)BT * VV;
    const long osz = (long)(unsigned)out_size;
    float* logits_dst = (osz >= BTV) ? out : logits;

    embed_kernel<<<(BT * EE + 255) / 256, 256>>>(idx, tok, pos, x);

    dim3 gE(EE / 128, BT / 128, 1);
    dim3 gQKV(EE / 128, BT / 128, 3);
    dim3 gF(FF / 128, BT / 128, 1);
    dim3 gAV(1, TT / 128, BB * HH);
    dim3 gLM(VV / 128, BT / 128, 1);

    for (int l = 0; l < LL; l++) {
        long wofs = (long)l * EE * EE;
        ln_kernel<<<BT, 256>>>(x, ln1s + l * EE, ln1b + l * EE, h);
        gemm_qkv<<<gQKV, 256>>>(h, Wq + wofs, Wk + wofs, Wv + wofs,
                                q, k, v, bq + l * EE, bk + l * EE, bv + l * EE);

        attn_scores_kernel<<<dim3(TT, HH, BB), 256>>>(q, k, attn);

        gemm128<<<gAV, 256>>>(attn, v, o, nullptr, TT, HD, TT, TT, EE, EE,
                              (long)TT * TT, (long)TT * EE, HD, (long)TT * EE, HD, HH, 0);

        gemm128<<<gE, 256>>>(o, Wo + wofs, x, bo + l * EE, BT, EE, EE, EE, EE, EE,
                             0, 0, 0, 0, 0, 1, FLAG_ACCUM);

        ln_kernel<<<BT, 256>>>(x, ln2s + l * EE, ln2b + l * EE, h);
        gemm128<<<gF, 256>>>(h, w1 + (long)l * EE * FF, mlp, b1 + (long)l * FF,
                             BT, FF, EE, EE, FF, FF, 0, 0, 0, 0, 0, 1, FLAG_RELU);
        gemm128<<<gE, 256>>>(mlp, w2 + (long)l * FF * EE, x, b2 + l * EE,
                             BT, EE, FF, FF, EE, EE, 0, 0, 0, 0, 0, 1, FLAG_ACCUM);
    }

    ln_kernel<<<BT, 256>>>(x, lnfs, lnfb, h);
    gemm128<<<gLM, 256>>>(h, Wlm, logits_dst, blm, BT, VV, EE, EE, VV, VV, 0, 0, 0, 0, 0, 1, 0);

    lossrow_kernel<<<BT, 256>>>(logits_dst, tgt, lrow);
    if (osz > BTV) {
        lossfinal_kernel<<<1, 256>>>(lrow, out + BTV, osz - BTV);
    } else if (osz < BTV) {
        lossfinal_kernel<<<1, 256>>>(lrow, out, osz);
    }
}

// round 17
// speedup vs baseline: 7.7593x; 2.5052x over previous
#include <cuda_runtime.h>
#include <cuda_fp16.h>
#include <math.h>
#include <stdint.h>

// Problem dims
#define BB 4
#define TT 1024
#define EE 768
#define HH 6
#define HD 128
#define LL 6
#define VV 32000
#define BT (BB*TT)   // 4096
#define FF (4*EE)    // 3072

// Scratch (device globals -- no runtime allocation allowed)
__device__ float g_x[BT*EE];
__device__ float g_h[BT*EE];
__device__ float g_q[BT*EE];
__device__ float g_k[BT*EE];
__device__ float g_v[BT*EE];
__device__ float g_o[BT*EE];
__device__ float g_attn[(long)BB*HH*TT*TT];
__device__ float g_mlp[BT*FF];
__device__ float g_logits[(long)BT*VV];
__device__ float g_lossrow[BT];

#define FLAG_RELU  1
#define FLAG_ACCUM 2
#define FLAG_TRIK  4   // causal: limit K to (blockIdx.y+1)*128

#define K2STRIDE 136   // uint32 units; 136 mod 32 = 8 -> fragment loads conflict-free

__device__ __forceinline__ uint32_t packh2(float lo, float hi) {
    __half2 h = __floats2half2_rn(lo, hi);   // .x = lo (low half)
    return *(uint32_t*)&h;
}

__device__ __forceinline__ void mma_f16(float c[4], uint32_t a0, uint32_t a1,
                                        uint32_t a2, uint32_t a3,
                                        uint32_t b0, uint32_t b1) {
    asm volatile(
        "mma.sync.aligned.m16n8k16.row.col.f32.f16.f16.f32 "
        "{%0,%1,%2,%3}, {%4,%5,%6,%7}, {%8,%9}, {%0,%1,%2,%3};\n"
        : "+f"(c[0]), "+f"(c[1]), "+f"(c[2]), "+f"(c[3])
        : "r"(a0), "r"(a1), "r"(a2), "r"(a3), "r"(b0), "r"(b1));
}

// ---------------------------------------------------------------------------
// FP16 tensor-core GEMM core: 128x128 block tile, K-step 32, double-buffered
// smem, one __syncthreads per K-iter, 2 CTAs/SM.
// ---------------------------------------------------------------------------
struct GemmSmem {
    uint32_t As[2][16][K2STRIDE];
    uint32_t Bs[2][16][K2STRIDE];
};

__device__ __forceinline__ void gemm_core(
    const float* __restrict__ Ab, const float* __restrict__ Bb,
    float* __restrict__ Cb, const float* __restrict__ bias,
    int K, int lda, int ldb, int ldc, int m0, int n0, int flags, GemmSmem& sm)
{
    const int tid  = threadIdx.x;
    const int lane = tid & 31;
    const int wid  = tid >> 5;
    const int warp_m = wid & 1;
    const int warp_n = wid >> 1;

    const int a_r  = tid >> 1;
    const int a_k2 = (tid & 1) * 8;
    const int b_k2 = tid >> 4;
    const int b_ng = (tid & 15) * 8;

    const int fr = lane >> 2;
    const int fc = lane & 3;

    float acc[4][4][4];
    #pragma unroll
    for (int i = 0; i < 4; i++)
        #pragma unroll
        for (int j = 0; j < 4; j++)
            #pragma unroll
            for (int u = 0; u < 4; u++) acc[i][j][u] = 0.f;

    float4 av[4];
    float4 be0, be1, bo0, bo1;

    #pragma unroll
    for (int i = 0; i < 4; i++)
        av[i] = *(const float4*)&Ab[(long)(m0 + a_r) * lda + a_k2 * 2 + i * 4];
    {
        const float* br0 = &Bb[(long)(2 * b_k2) * ldb + n0 + b_ng];
        const float* br1 = br0 + ldb;
        be0 = *(const float4*)br0; be1 = *(const float4*)(br0 + 4);
        bo0 = *(const float4*)br1; bo1 = *(const float4*)(br1 + 4);
    }
    #pragma unroll
    for (int i = 0; i < 4; i++) {
        sm.As[0][a_k2 + 2*i    ][a_r] = packh2(av[i].x, av[i].y);
        sm.As[0][a_k2 + 2*i + 1][a_r] = packh2(av[i].z, av[i].w);
    }
    {
        uint4 p0, p1;
        p0.x = packh2(be0.x, bo0.x); p0.y = packh2(be0.y, bo0.y);
        p0.z = packh2(be0.z, bo0.z); p0.w = packh2(be0.w, bo0.w);
        p1.x = packh2(be1.x, bo1.x); p1.y = packh2(be1.y, bo1.y);
        p1.z = packh2(be1.z, bo1.z); p1.w = packh2(be1.w, bo1.w);
        *(uint4*)&sm.Bs[0][b_k2][b_ng]     = p0;
        *(uint4*)&sm.Bs[0][b_k2][b_ng + 4] = p1;
    }
    __syncthreads();

    int s = 0;
    for (int kt = 0; kt < K; kt += 32) {
        const bool has_next = (kt + 32) < K;
        if (has_next) {
            #pragma unroll
            for (int i = 0; i < 4; i++)
                av[i] = *(const float4*)&Ab[(long)(m0 + a_r) * lda + kt + 32 + a_k2 * 2 + i * 4];
            const float* br0 = &Bb[(long)(kt + 32 + 2 * b_k2) * ldb + n0 + b_ng];
            const float* br1 = br0 + ldb;
            be0 = *(const float4*)br0; be1 = *(const float4*)(br0 + 4);
            bo0 = *(const float4*)br1; bo1 = *(const float4*)(br1 + 4);
        }

        const uint32_t (*As_s)[K2STRIDE] = sm.As[s];
        const uint32_t (*Bs_s)[K2STRIDE] = sm.Bs[s];
        #pragma unroll
        for (int ks = 0; ks < 2; ks++) {
            const int kk2 = ks * 8;
            uint32_t afr[4][4];
            #pragma unroll
            for (int mt = 0; mt < 4; mt++) {
                int mb = warp_m * 64 + mt * 16 + fr;
                afr[mt][0] = As_s[kk2 + fc    ][mb];
                afr[mt][1] = As_s[kk2 + fc    ][mb + 8];
                afr[mt][2] = As_s[kk2 + 4 + fc][mb];
                afr[mt][3] = As_s[kk2 + 4 + fc][mb + 8];
            }
            uint32_t bfr[4][2];
            #pragma unroll
            for (int nt = 0; nt < 4; nt++) {
                int nb = warp_n * 32 + nt * 8 + fr;
                bfr[nt][0] = Bs_s[kk2 + fc    ][nb];
                bfr[nt][1] = Bs_s[kk2 + 4 + fc][nb];
            }
            #pragma unroll
            for (int mt = 0; mt < 4; mt++)
                #pragma unroll
                for (int nt = 0; nt < 4; nt++)
                    mma_f16(acc[mt][nt], afr[mt][0], afr[mt][1], afr[mt][2], afr[mt][3],
                            bfr[nt][0], bfr[nt][1]);
        }

        if (has_next) {
            const int ns = s ^ 1;
            #pragma unroll
            for (int i = 0; i < 4; i++) {
                sm.As[ns][a_k2 + 2*i    ][a_r] = packh2(av[i].x, av[i].y);
                sm.As[ns][a_k2 + 2*i + 1][a_r] = packh2(av[i].z, av[i].w);
            }
            uint4 p0, p1;
            p0.x = packh2(be0.x, bo0.x); p0.y = packh2(be0.y, bo0.y);
            p0.z = packh2(be0.z, bo0.z); p0.w = packh2(be0.w, bo0.w);
            p1.x = packh2(be1.x, bo1.x); p1.y = packh2(be1.y, bo1.y);
            p1.z = packh2(be1.z, bo1.z); p1.w = packh2(be1.w, bo1.w);
            *(uint4*)&sm.Bs[ns][b_k2][b_ng]     = p0;
            *(uint4*)&sm.Bs[ns][b_k2][b_ng + 4] = p1;
            __syncthreads();
            s = ns;
        }
    }

    #pragma unroll
    for (int nt = 0; nt < 4; nt++) {
        const int col = n0 + warp_n * 32 + nt * 8 + fc * 2;
        float bj0 = bias ? bias[col]     : 0.f;
        float bj1 = bias ? bias[col + 1] : 0.f;
        #pragma unroll
        for (int mt = 0; mt < 4; mt++) {
            const int row = m0 + warp_m * 64 + mt * 16 + fr;
            #pragma unroll
            for (int half = 0; half < 2; half++) {
                long base = (long)(row + half * 8) * ldc + col;
                float v0 = acc[mt][nt][half * 2 + 0] + bj0;
                float v1 = acc[mt][nt][half * 2 + 1] + bj1;
                if (flags & FLAG_ACCUM) { v0 += Cb[base]; v1 += Cb[base + 1]; }
                if (flags & FLAG_RELU)  { v0 = fmaxf(v0, 0.f); v1 = fmaxf(v1, 0.f); }
                Cb[base]     = v0;
                Cb[base + 1] = v1;
            }
        }
    }
}

// Generic strided/batched wrapper (FLAG_TRIK limits K for causal AV)
__global__ __launch_bounds__(256, 2) void gemm128(
    const float* __restrict__ A, const float* __restrict__ B,
    float* __restrict__ C, const float* __restrict__ bias,
    int M, int N, int K, int lda, int ldb, int ldc,
    long sA, long sBo, long sBi, long sCo, long sCi, int zdiv, int flags)
{
    __shared__ GemmSmem sm;
    const int z = blockIdx.z;
    const float* Ab = A + (long)z * sA;
    const float* Bb = B + (long)(z / zdiv) * sBo + (long)(z % zdiv) * sBi;
    float*       Cb = C + (long)(z / zdiv) * sCo + (long)(z % zdiv) * sCi;
    int Keff = (flags & FLAG_TRIK) ? min(K, ((int)blockIdx.y + 1) * 128) : K;
    gemm_core(Ab, Bb, Cb, bias, Keff, lda, ldb, ldc,
              blockIdx.y * 128, blockIdx.x * 128, flags, sm);
}

// Fused QKV: z in {0,1,2} selects weight/output set (wave packing)
__global__ __launch_bounds__(256, 2) void gemm_qkv(
    const float* __restrict__ A,
    const float* __restrict__ B0, const float* __restrict__ B1, const float* __restrict__ B2,
    float* __restrict__ C0, float* __restrict__ C1, float* __restrict__ C2,
    const float* __restrict__ bi0, const float* __restrict__ bi1, const float* __restrict__ bi2)
{
    __shared__ GemmSmem sm;
    const int z = blockIdx.z;
    const float* Bb = (z == 0) ? B0 : (z == 1) ? B1 : B2;
    float*       Cb = (z == 0) ? C0 : (z == 1) ? C1 : C2;
    const float* bi = (z == 0) ? bi0 : (z == 1) ? bi1 : bi2;
    gemm_core(A, Bb, Cb, bi, EE, EE, EE, EE,
              blockIdx.y * 128, blockIdx.x * 128, 0, sm);
}

// ---------------------------------------------------------------------------
// QK^T GEMM: S[q][k] = sum_d Q[q][d]*K[k][d] per (b,h). B staged transposed
// from row-major K tokens (same staging pattern as A). Upper-triangle tiles
// early-exit. Raw scores written (scale+mask applied in softmax).
// ---------------------------------------------------------------------------
__global__ __launch_bounds__(256, 2) void gemm_qkT(
    const float* __restrict__ Q, const float* __restrict__ Km, float* __restrict__ P)
{
    __shared__ GemmSmem sm;
    const int z = blockIdx.z;            // b*HH + h
    const int m0 = blockIdx.y * 128;     // queries
    const int n0 = blockIdx.x * 128;     // keys
    if (n0 > m0) return;                 // fully masked tile

    const int b = z / HH, h = z % HH;
    const float* Ab = Q  + (long)(b * TT) * EE + h * HD;
    const float* Bb = Km + (long)(b * TT) * EE + h * HD;
    float*       Cb = P  + (long)z * TT * TT;

    const int tid  = threadIdx.x;
    const int lane = tid & 31;
    const int wid  = tid >> 5;
    const int warp_m = wid & 1;
    const int warp_n = wid >> 1;

    const int a_r  = tid >> 1;           // row 0..127 (used for both Q and K rows)
    const int a_k2 = (tid & 1) * 8;      // k2 offset 0/8

    const int fr = lane >> 2;
    const int fc = lane & 3;

    float acc[4][4][4];
    #pragma unroll
    for (int i = 0; i < 4; i++)
        #pragma unroll
        for (int j = 0; j < 4; j++)
            #pragma unroll
            for (int u = 0; u < 4; u++) acc[i][j][u] = 0.f;

    float4 av[4], bv[4];

    // Prologue: stage 0 (kt=0)
    #pragma unroll
    for (int i = 0; i < 4; i++) {
        av[i] = *(const float4*)&Ab[(long)(m0 + a_r) * EE + a_k2 * 2 + i * 4];
        bv[i] = *(const float4*)&Bb[(long)(n0 + a_r) * EE + a_k2 * 2 + i * 4];
    }
    #pragma unroll
    for (int i = 0; i < 4; i++) {
        sm.As[0][a_k2 + 2*i    ][a_r] = packh2(av[i].x, av[i].y);
        sm.As[0][a_k2 + 2*i + 1][a_r] = packh2(av[i].z, av[i].w);
        sm.Bs[0][a_k2 + 2*i    ][a_r] = packh2(bv[i].x, bv[i].y);
        sm.Bs[0][a_k2 + 2*i + 1][a_r] = packh2(bv[i].z, bv[i].w);
    }
    __syncthreads();

    int s = 0;
    for (int kt = 0; kt < HD; kt += 32) {
        const bool has_next = (kt + 32) < HD;
        if (has_next) {
            #pragma unroll
            for (int i = 0; i < 4; i++) {
                av[i] = *(const float4*)&Ab[(long)(m0 + a_r) * EE + kt + 32 + a_k2 * 2 + i * 4];
                bv[i] = *(const float4*)&Bb[(long)(n0 + a_r) * EE + kt + 32 + a_k2 * 2 + i * 4];
            }
        }

        const uint32_t (*As_s)[K2STRIDE] = sm.As[s];
        const uint32_t (*Bs_s)[K2STRIDE] = sm.Bs[s];
        #pragma unroll
        for (int ks = 0; ks < 2; ks++) {
            const int kk2 = ks * 8;
            uint32_t afr[4][4];
            #pragma unroll
            for (int mt = 0; mt < 4; mt++) {
                int mb = warp_m * 64 + mt * 16 + fr;
                afr[mt][0] = As_s[kk2 + fc    ][mb];
                afr[mt][1] = As_s[kk2 + fc    ][mb + 8];
                afr[mt][2] = As_s[kk2 + 4 + fc][mb];
                afr[mt][3] = As_s[kk2 + 4 + fc][mb + 8];
            }
            uint32_t bfr[4][2];
            #pragma unroll
            for (int nt = 0; nt < 4; nt++) {
                int nb = warp_n * 32 + nt * 8 + fr;
                bfr[nt][0] = Bs_s[kk2 + fc    ][nb];
                bfr[nt][1] = Bs_s[kk2 + 4 + fc][nb];
            }
            #pragma unroll
            for (int mt = 0; mt < 4; mt++)
                #pragma unroll
                for (int nt = 0; nt < 4; nt++)
                    mma_f16(acc[mt][nt], afr[mt][0], afr[mt][1], afr[mt][2], afr[mt][3],
                            bfr[nt][0], bfr[nt][1]);
        }

        if (has_next) {
            const int ns = s ^ 1;
            #pragma unroll
            for (int i = 0; i < 4; i++) {
                sm.As[ns][a_k2 + 2*i    ][a_r] = packh2(av[i].x, av[i].y);
                sm.As[ns][a_k2 + 2*i + 1][a_r] = packh2(av[i].z, av[i].w);
                sm.Bs[ns][a_k2 + 2*i    ][a_r] = packh2(bv[i].x, bv[i].y);
                sm.Bs[ns][a_k2 + 2*i + 1][a_r] = packh2(bv[i].z, bv[i].w);
            }
            __syncthreads();
            s = ns;
        }
    }

    #pragma unroll
    for (int nt = 0; nt < 4; nt++) {
        const int col = n0 + warp_n * 32 + nt * 8 + fc * 2;
        #pragma unroll
        for (int mt = 0; mt < 4; mt++) {
            const int row = m0 + warp_m * 64 + mt * 16 + fr;
            #pragma unroll
            for (int half = 0; half < 2; half++) {
                long base = (long)(row + half * 8) * TT + col;
                Cb[base]     = acc[mt][nt][half * 2 + 0];
                Cb[base + 1] = acc[mt][nt][half * 2 + 1];
            }
        }
    }
}

// ---------------------------------------------------------------------------
// Causal softmax over precomputed scores (in-place on P). One block per row.
// ---------------------------------------------------------------------------
__global__ __launch_bounds__(256) void softmax_causal(float* __restrict__ P)
{
    __shared__ float red[256];
    const int qi = blockIdx.x;
    const int tid = threadIdx.x;
    float* row = P + (long)blockIdx.y * TT * TT + (long)qi * TT;
    const float scale = 0.08838834764831845f;   // 1/sqrt(128)

    float sc[4];
    float lm = -1e30f;
    #pragma unroll
    for (int j = 0; j < 4; j++) {
        int key = tid + j * 256;
        if (key <= qi) { sc[j] = row[key] * scale; lm = fmaxf(lm, sc[j]); }
        else sc[j] = -1e30f;
    }
    red[tid] = lm; __syncthreads();
    for (int st = 128; st > 0; st >>= 1) { if (tid < st) red[tid] = fmaxf(red[tid], red[tid + st]); __syncthreads(); }
    float m = red[0];
    __syncthreads();

    float ssum = 0.f;
    #pragma unroll
    for (int j = 0; j < 4; j++) {
        if (sc[j] > -1e29f) { sc[j] = expf(sc[j] - m); ssum += sc[j]; }
        else sc[j] = 0.f;
    }
    red[tid] = ssum; __syncthreads();
    for (int st = 128; st > 0; st >>= 1) { if (tid < st) red[tid] += red[tid + st]; __syncthreads(); }
    float sinv = 1.f / red[0];

    #pragma unroll
    for (int j = 0; j < 4; j++)
        row[tid + j * 256] = sc[j] * sinv;
}

// ---------------------------------------------------------------------------
// Embedding
// ---------------------------------------------------------------------------
__global__ void embed_kernel(const int* __restrict__ idx,
                             const float* __restrict__ tok,
                             const float* __restrict__ pos,
                             float* __restrict__ x)
{
    long i = (long)blockIdx.x * 256 + threadIdx.x;
    if (i >= (long)BT * EE) return;
    int row = (int)(i / EE);
    int col = (int)(i % EE);
    long tkn = idx[row];
    tkn = ((tkn % VV) + VV) % VV;
    x[i] = tok[tkn * EE + col] + pos[(long)(row % TT) * EE + col];
}

// ---------------------------------------------------------------------------
// LayerNorm
// ---------------------------------------------------------------------------
__global__ __launch_bounds__(256) void ln_kernel(
    const float* __restrict__ x, const float* __restrict__ s,
    const float* __restrict__ b, float* __restrict__ o)
{
    __shared__ float red[256];
    const int row = blockIdx.x;
    const int tid = threadIdx.x;
    const float* xr = x + (long)row * EE;

    float ls = 0.f;
    for (int c = tid; c < EE; c += 256) ls += xr[c];
    red[tid] = ls; __syncthreads();
    for (int st = 128; st > 0; st >>= 1) { if (tid < st) red[tid] += red[tid + st]; __syncthreads(); }
    float mu = red[0] / EE;
    __syncthreads();

    float lv = 0.f;
    for (int c = tid; c < EE; c += 256) { float d = xr[c] - mu; lv += d * d; }
    red[tid] = lv; __syncthreads();
    for (int st = 128; st > 0; st >>= 1) { if (tid < st) red[tid] += red[tid + st]; __syncthreads(); }
    float rs = rsqrtf(red[0] / EE + 1e-5f);

    float* orow = o + (long)row * EE;
    for (int c = tid; c < EE; c += 256)
        orow[c] = (xr[c] - mu) * rs * s[c] + b[c];
}

// ---------------------------------------------------------------------------
// Loss
// ---------------------------------------------------------------------------
__global__ __launch_bounds__(256) void lossrow_kernel(
    const float* __restrict__ logits, const int* __restrict__ tgt,
    float* __restrict__ lossrow)
{
    __shared__ float red[256];
    const int row = blockIdx.x;
    const int tid = threadIdx.x;
    const float* lr = logits + (long)row * VV;

    float lm = -1e30f;
    for (int c = tid; c < VV; c += 256) lm = fmaxf(lm, lr[c]);
    red[tid] = lm; __syncthreads();
    for (int st = 128; st > 0; st >>= 1) { if (tid < st) red[tid] = fmaxf(red[tid], red[tid + st]); __syncthreads(); }
    float m = red[0];
    __syncthreads();

    float ls = 0.f;
    for (int c = tid; c < VV; c += 256) ls += expf(lr[c] - m);
    red[tid] = ls; __syncthreads();
    for (int st = 128; st > 0; st >>= 1) { if (tid < st) red[tid] += red[tid + st]; __syncthreads(); }

    if (tid == 0) {
        long t = tgt[row];
        t = ((t % VV) + VV) % VV;
        lossrow[row] = lr[t] - m - logf(red[0]);
    }
}

__global__ __launch_bounds__(256) void lossfinal_kernel(
    const float* __restrict__ lossrow, float* __restrict__ dst, long count)
{
    __shared__ float red[256];
    const int tid = threadIdx.x;
    float ls = 0.f;
    for (int r = tid; r < BT; r += 256) ls += lossrow[r];
    red[tid] = ls; __syncthreads();
    for (int st = 128; st > 0; st >>= 1) { if (tid < st) red[tid] += red[tid + st]; __syncthreads(); }
    float loss = -red[0] / (float)BT;
    for (long i = tid; i < count; i += 256) dst[i] = loss;
}

// ---------------------------------------------------------------------------
// Host orchestration
// ---------------------------------------------------------------------------
extern "C" void kernel_launch(void* const* d_in, const int* in_sizes, int n_in,
                              void* d_out, int out_size)
{
    const int* idx = (const int*)d_in[0];
    const int* tgt = (const int*)d_in[1];
    const float* tok  = (const float*)d_in[2];
    const float* pos  = (const float*)d_in[3];
    const float* Wq   = (const float*)d_in[4];
    const float* bq   = (const float*)d_in[5];
    const float* Wk   = (const float*)d_in[6];
    const float* bk   = (const float*)d_in[7];
    const float* Wv   = (const float*)d_in[8];
    const float* bv   = (const float*)d_in[9];
    const float* Wo   = (const float*)d_in[10];
    const float* bo   = (const float*)d_in[11];
    const float* w1   = (const float*)d_in[12];
    const float* b1   = (const float*)d_in[13];
    const float* w2   = (const float*)d_in[14];
    const float* b2   = (const float*)d_in[15];
    const float* ln1s = (const float*)d_in[16];
    const float* ln1b = (const float*)d_in[17];
    const float* ln2s = (const float*)d_in[18];
    const float* ln2b = (const float*)d_in[19];
    const float* lnfs = (const float*)d_in[20];
    const float* lnfb = (const float*)d_in[21];
    const float* Wlm  = (const float*)d_in[22];
    const float* blm  = (const float*)d_in[23];
    float* out = (float*)d_out;

    float *x, *h, *q, *k, *v, *o, *attn, *mlp, *logits, *lrow;
    cudaGetSymbolAddress((void**)&x,      g_x);
    cudaGetSymbolAddress((void**)&h,      g_h);
    cudaGetSymbolAddress((void**)&q,      g_q);
    cudaGetSymbolAddress((void**)&k,      g_k);
    cudaGetSymbolAddress((void**)&v,      g_v);
    cudaGetSymbolAddress((void**)&o,      g_o);
    cudaGetSymbolAddress((void**)&attn,   g_attn);
    cudaGetSymbolAddress((void**)&mlp,    g_mlp);
    cudaGetSymbolAddress((void**)&logits, g_logits);
    cudaGetSymbolAddress((void**)&lrow,   g_lossrow);

    const long BTV = (long)BT * VV;
    const long osz = (long)(unsigned)out_size;
    float* logits_dst = (osz >= BTV) ? out : logits;

    embed_kernel<<<(BT * EE + 255) / 256, 256>>>(idx, tok, pos, x);

    dim3 gE(EE / 128, BT / 128, 1);
    dim3 gQKV(EE / 128, BT / 128, 3);
    dim3 gF(FF / 128, BT / 128, 1);
    dim3 gQK(TT / 128, TT / 128, BB * HH);
    dim3 gSM(TT, BB * HH, 1);
    dim3 gAV(1, TT / 128, BB * HH);
    dim3 gLM(VV / 128, BT / 128, 1);

    for (int l = 0; l < LL; l++) {
        long wofs = (long)l * EE * EE;
        ln_kernel<<<BT, 256>>>(x, ln1s + l * EE, ln1b + l * EE, h);
        gemm_qkv<<<gQKV, 256>>>(h, Wq + wofs, Wk + wofs, Wv + wofs,
                                q, k, v, bq + l * EE, bk + l * EE, bv + l * EE);

        gemm_qkT<<<gQK, 256>>>(q, k, attn);
        softmax_causal<<<gSM, 256>>>(attn);

        gemm128<<<gAV, 256>>>(attn, v, o, nullptr, TT, HD, TT, TT, EE, EE,
                              (long)TT * TT, (long)TT * EE, HD, (long)TT * EE, HD, HH,
                              FLAG_TRIK);

        gemm128<<<gE, 256>>>(o, Wo + wofs, x, bo + l * EE, BT, EE, EE, EE, EE, EE,
                             0, 0, 0, 0, 0, 1, FLAG_ACCUM);

        ln_kernel<<<BT, 256>>>(x, ln2s + l * EE, ln2b + l * EE, h);
        gemm128<<<gF, 256>>>(h, w1 + (long)l * EE * FF, mlp, b1 + (long)l * FF,
                             BT, FF, EE, EE, FF, FF, 0, 0, 0, 0, 0, 1, FLAG_RELU);
        gemm128<<<gE, 256>>>(mlp, w2 + (long)l * FF * EE, x, b2 + l * EE,
                             BT, EE, FF, FF, EE, EE, 0, 0, 0, 0, 0, 1, FLAG_ACCUM);
    }

    ln_kernel<<<BT, 256>>>(x, lnfs, lnfb, h);
    gemm128<<<gLM, 256>>>(h, Wlm, logits_dst, blm, BT, VV, EE, EE, VV, VV, 0, 0, 0, 0, 0, 1, 0);

    lossrow_kernel<<<BT, 256>>>(logits_dst, tgt, lrow);
    if (osz > BTV) {
        lossfinal_kernel<<<1, 256>>>(lrow, out + BTV, osz - BTV);
    } else if (osz < BTV) {
        lossfinal_kernel<<<1, 256>>>(lrow, out, osz);
    }
}